// round 14
// baseline (speedup 1.0000x reference)
#include <cuda_runtime.h>
#include <cuda_bf16.h>
#include <math.h>
#include <stdint.h>

// Problem dims
#define BB 256
#define LL 128
#define DD 1024
#define HH 512
#define G4H 2048
#define GNF 4096
#define KS2 2048            // compact [hi|lo] storage K
#define MM_TOT (LL * BB)

// ---------------- scratch (device globals) ----------------------------------
__device__ float g_G[(size_t)MM_TOT * GNF];
__device__ float g_outd[2][(size_t)BB * LL * HH];
__device__ __nv_bfloat16 g_hhi[2][2][(size_t)BB * HH];
__device__ __nv_bfloat16 g_hlo[2][2][(size_t)BB * HH];
__device__ __nv_bfloat16 g_Xs[(size_t)MM_TOT * KS2];   // [m][ hi(1024) | lo(1024) ]
__device__ __nv_bfloat16 g_Ws[(size_t)GNF * KS2];      // [c][ hi(1024) | lo(1024) ]
__device__ __nv_bfloat16 g_Whh[2][(size_t)G4H * 1024];
__device__ float g_bias[GNF];

struct GrpBar { unsigned int cnt; unsigned int gen; unsigned int pad[62]; };
__device__ GrpBar g_bars[8];

// ---------------- helpers ----------------------------------------------------
__device__ __forceinline__ uint32_t smem_u32(const void* p) {
    uint32_t a;
    asm("{ .reg .u64 t; cvta.to.shared.u64 t, %1; cvt.u32.u64 %0, t; }"
        : "=r"(a) : "l"(p));
    return a;
}
#define CPA16(dst, src) \
    asm volatile("cp.async.ca.shared.global [%0], [%1], 16;" :: "r"(dst), "l"(src))
#define CPA_COMMIT() asm volatile("cp.async.commit_group;" ::: "memory")

__device__ __forceinline__ void ldmatrix_x4(uint32_t* r, uint32_t addr) {
    asm volatile("ldmatrix.sync.aligned.m8n8.x4.shared.b16 {%0,%1,%2,%3}, [%4];"
                 : "=r"(r[0]), "=r"(r[1]), "=r"(r[2]), "=r"(r[3]) : "r"(addr));
}
__device__ __forceinline__ void mma16816(float* c, const uint32_t* a,
                                         uint32_t b0, uint32_t b1) {
    asm volatile(
        "mma.sync.aligned.m16n8k16.row.col.f32.bf16.bf16.f32 "
        "{%0,%1,%2,%3}, {%4,%5,%6,%7}, {%8,%9}, {%0,%1,%2,%3};"
        : "+f"(c[0]), "+f"(c[1]), "+f"(c[2]), "+f"(c[3])
        : "r"(a[0]), "r"(a[1]), "r"(a[2]), "r"(a[3]), "r"(b0), "r"(b1));
}
__device__ __forceinline__ float fsigmoid(float x) {
    return __fdividef(1.f, 1.f + __expf(-x));
}
__device__ __forceinline__ float ftanh(float x) {
    float e2 = __expf(2.f * x);
    return __fdividef(e2 - 1.f, e2 + 1.f);
}

__device__ __forceinline__ void group_barrier(int gid, int step) {
    __syncthreads();
    if (threadIdx.x == 0) {
        __threadfence();
        unsigned int a = atomicAdd(&g_bars[gid].cnt, 1u);
        if (a == 31u) {
            g_bars[gid].cnt = 0;
            __threadfence();
            atomicExch(&g_bars[gid].gen, (unsigned)(step + 1));
        } else {
            unsigned int g;
            do {
                asm volatile("ld.acquire.gpu.u32 %0, [%1];"
                             : "=r"(g) : "l"(&g_bars[gid].gen));
                if (g > (unsigned)step) break;
                __nanosleep(32);
            } while (true);
        }
    }
    __syncthreads();
}

// ---------------- init -------------------------------------------------------
__global__ void init_hc_kernel() {
    int i = blockIdx.x * blockDim.x + threadIdx.x;
    if (i < 8) { g_bars[i].cnt = 0; g_bars[i].gen = 0; }
    if (i < BB * HH) {
        g_hhi[0][0][i] = __float2bfloat16_rn(0.f);
        g_hhi[1][0][i] = __float2bfloat16_rn(0.f);
        g_hlo[0][0][i] = __float2bfloat16_rn(0.f);
        g_hlo[1][0][i] = __float2bfloat16_rn(0.f);
    }
}

// ---------------- fp32 -> bf16 hi/lo split converters ------------------------
__global__ __launch_bounds__(256)
void convert_x_kernel(const float* __restrict__ X) {
    const int bt = blockIdx.x;
    const int b = bt >> 7;
    const int t = bt & 127;
    const float4 v = ((const float4*)(X + (size_t)bt * DD))[threadIdx.x];
    __nv_bfloat16 hi4[4], lo4[4];
    hi4[0] = __float2bfloat16_rn(v.x); lo4[0] = __float2bfloat16_rn(v.x - __bfloat162float(hi4[0]));
    hi4[1] = __float2bfloat16_rn(v.y); lo4[1] = __float2bfloat16_rn(v.y - __bfloat162float(hi4[1]));
    hi4[2] = __float2bfloat16_rn(v.z); lo4[2] = __float2bfloat16_rn(v.z - __bfloat162float(hi4[2]));
    hi4[3] = __float2bfloat16_rn(v.w); lo4[3] = __float2bfloat16_rn(v.w - __bfloat162float(hi4[3]));
    const size_t base = ((size_t)t * BB + b) * KS2 + threadIdx.x * 4;
    *(uint2*)&g_Xs[base]      = *(const uint2*)hi4;
    *(uint2*)&g_Xs[base + DD] = *(const uint2*)lo4;
}

__global__ __launch_bounds__(256)
void convert_w_kernel(const float* __restrict__ Wf, const float* __restrict__ Wb,
                      const float* __restrict__ bf, const float* __restrict__ bb) {
    const int c = blockIdx.x;
    const int dir = (c >= G4H);
    const int local = c - dir * G4H;
    const int j = local >> 2, gate = local & 3;
    const int srow = gate * HH + j;
    const float* src = dir ? (Wb + (size_t)srow * DD) : (Wf + (size_t)srow * DD);
    const float4 v = ((const float4*)src)[threadIdx.x];
    __nv_bfloat16 hi4[4], lo4[4];
    hi4[0] = __float2bfloat16_rn(v.x); lo4[0] = __float2bfloat16_rn(v.x - __bfloat162float(hi4[0]));
    hi4[1] = __float2bfloat16_rn(v.y); lo4[1] = __float2bfloat16_rn(v.y - __bfloat162float(hi4[1]));
    hi4[2] = __float2bfloat16_rn(v.z); lo4[2] = __float2bfloat16_rn(v.z - __bfloat162float(hi4[2]));
    hi4[3] = __float2bfloat16_rn(v.w); lo4[3] = __float2bfloat16_rn(v.w - __bfloat162float(hi4[3]));
    const size_t base = (size_t)c * KS2 + threadIdx.x * 4;
    *(uint2*)&g_Ws[base]      = *(const uint2*)hi4;
    *(uint2*)&g_Ws[base + DD] = *(const uint2*)lo4;
    if (threadIdx.x == 0)
        g_bias[c] = dir ? bb[srow] : bf[srow];
}

__global__ __launch_bounds__(128)
void convert_whh_kernel(const float* __restrict__ Wf, const float* __restrict__ Wb) {
    const int c   = blockIdx.x;
    const int dir = blockIdx.y;
    const int gate = c & 3, j = c >> 2;
    const float* __restrict__ W = dir ? Wb : Wf;
    const float4 v = ((const float4*)(W + (size_t)(gate * HH + j) * HH))[threadIdx.x];
    __nv_bfloat16 hi4[4], lo4[4];
    hi4[0] = __float2bfloat16_rn(v.x); lo4[0] = __float2bfloat16_rn(v.x - __bfloat162float(hi4[0]));
    hi4[1] = __float2bfloat16_rn(v.y); lo4[1] = __float2bfloat16_rn(v.y - __bfloat162float(hi4[1]));
    hi4[2] = __float2bfloat16_rn(v.z); lo4[2] = __float2bfloat16_rn(v.z - __bfloat162float(hi4[2]));
    hi4[3] = __float2bfloat16_rn(v.w); lo4[3] = __float2bfloat16_rn(v.w - __bfloat162float(hi4[3]));
    __nv_bfloat16* dst = &g_Whh[dir][(size_t)c * 1024];
    *(uint2*)&dst[threadIdx.x * 4]       = *(const uint2*)hi4;
    *(uint2*)&dst[512 + threadIdx.x * 4] = *(const uint2*)lo4;
}

// ---------------- input-projection GEMM (R13 winner, unchanged) --------------
#define SROW2 144
#define GA_TILE (128 * SROW2)
#define GB_TILE (256 * SROW2)
#define GSTG (GA_TILE + GB_TILE)
#define G_SMEM (3 * GSTG)
#define GKT 48

__global__ __launch_bounds__(512, 1)
void gemm_mma_kernel() {
    extern __shared__ __align__(16) char sm[];
    const uint32_t sbase = smem_u32(sm);

    const int tid  = threadIdx.x;
    const int wid  = tid >> 5;
    const int lane = tid & 31;
    const int nTile = blockIdx.x * 256;
    const int mTile = blockIdx.y * 128;

    const int m0 = (wid & 1) * 64;
    const int n0 = (wid >> 1) * 32;

    const int lc8 = tid & 7;
    const int lr  = tid >> 3;
    const uint32_t aoff0 = (uint32_t)(lr * SROW2 + lc8 * 16);
    const uint32_t aoff1 = (uint32_t)((lr + 64) * SROW2 + lc8 * 16);
    const __nv_bfloat16* __restrict__ gA = g_Xs + (size_t)mTile * KS2;
    const __nv_bfloat16* __restrict__ gB = g_Ws + (size_t)nTile * KS2;

    auto issue_stage = [&](int kt) {
        const uint32_t sa = sbase + (kt % 3) * GSTG;
        const uint32_t sb = sa + GA_TILE;
        const int seg = kt >> 4;
        const int k64 = (kt & 15) * 64;
        const size_t acol = (size_t)((seg == 1) ? (DD + k64) : k64) + lc8 * 8;
        const size_t bcol = (size_t)((seg == 2) ? (DD + k64) : k64) + lc8 * 8;
        CPA16(sa + aoff0, gA + (size_t)lr * KS2 + acol);
        CPA16(sa + aoff1, gA + (size_t)(lr + 64) * KS2 + acol);
#pragma unroll
        for (int q = 0; q < 4; q++) {
            const int row = lr + q * 64;
            CPA16(sb + aoff0 + (uint32_t)(q * 64 * SROW2),
                  gB + (size_t)row * KS2 + bcol);
        }
    };

    float acc[4][4][4];
#pragma unroll
    for (int i = 0; i < 4; i++)
#pragma unroll
        for (int j = 0; j < 4; j++)
#pragma unroll
            for (int q = 0; q < 4; q++) acc[i][j][q] = 0.f;

    const int r8 = lane & 7;
    const int tI = lane >> 3;
    const uint32_t aLaneOff = (uint32_t)((r8 + (tI & 1) * 8) * SROW2 + (tI >> 1) * 16);
    const uint32_t bLaneOff = (uint32_t)((r8 + (tI >> 1) * 8) * SROW2 + (tI & 1) * 16);

    issue_stage(0); CPA_COMMIT();
    issue_stage(1); CPA_COMMIT();

    for (int kt = 0; kt < GKT; kt++) {
        asm volatile("cp.async.wait_group 1;" ::: "memory");
        __syncthreads();

        const uint32_t sa = sbase + (kt % 3) * GSTG;
        const uint32_t sb = sa + GA_TILE;
#pragma unroll
        for (int kk = 0; kk < 4; kk++) {
            uint32_t afr[4][4], bfr[2][4];
#pragma unroll
            for (int mi = 0; mi < 4; mi++)
                ldmatrix_x4(afr[mi],
                            sa + (uint32_t)((m0 + mi * 16) * SROW2 + kk * 32) + aLaneOff);
#pragma unroll
            for (int nb = 0; nb < 2; nb++)
                ldmatrix_x4(bfr[nb],
                            sb + (uint32_t)((n0 + nb * 16) * SROW2 + kk * 32) + bLaneOff);
#pragma unroll
            for (int mi = 0; mi < 4; mi++)
#pragma unroll
                for (int ni = 0; ni < 4; ni++) {
                    const uint32_t* bp = &bfr[ni >> 1][(ni & 1) * 2];
                    mma16816(acc[mi][ni], afr[mi], bp[0], bp[1]);
                }
        }
        if (kt + 2 < GKT) issue_stage(kt + 2);
        CPA_COMMIT();
    }

    const int gid = lane >> 2;
    const int tig = lane & 3;
#pragma unroll
    for (int mi = 0; mi < 4; mi++) {
        const int m = mTile + m0 + mi * 16 + gid;
#pragma unroll
        for (int ni = 0; ni < 4; ni++) {
            const int n = nTile + n0 + ni * 8 + tig * 2;
            const float2 bv = *(const float2*)&g_bias[n];
            float2 o0 = make_float2(acc[mi][ni][0] + bv.x, acc[mi][ni][1] + bv.y);
            float2 o1 = make_float2(acc[mi][ni][2] + bv.x, acc[mi][ni][3] + bv.y);
            *(float2*)&g_G[(size_t)m * GNF + n]       = o0;
            *(float2*)&g_G[(size_t)(m + 8) * GNF + n] = o1;
        }
    }
}

// ---------------- persistent recurrence: chunk-unified stages ----------------
// 8 K-chunks of 64. Each stage holds {Ahi|Alo|Bhi|Blo} (64 rows x 144B each).
// Products per chunk: P0=Ahi*Bhi (warps 0-3), P1=Alo*Bhi (warps 4-7),
// P2=Ahi*Blo (warps 0-3 on even chunks, 4-7 on odd). acc shared across products.
#define QSZ (64 * SROW2)           // 9216 per quarter
#define CH_ALO QSZ
#define CH_BHI (2 * QSZ)
#define CH_BLO (3 * QSZ)
#define CSTG (4 * QSZ)             // 36864 per chunk stage
#define R14_SMEM (3 * CSTG)        // 110592
#define NCH 8
#define SRBUF (64 * 68 * 4)        // 17408
#define SROFF (2 * CSTG)           // sR overlays stage 2

__global__ __launch_bounds__(256, 2)
void lstm_persistent(const int* __restrict__ x_len)
{
    extern __shared__ __align__(16) char sm[];
    const uint32_t sbase = smem_u32(sm);

    const int tid  = threadIdx.x;
    const int wid  = tid >> 5;
    const int lane = tid & 31;
    const int nTile = blockIdx.x * 64;
    const int b0    = blockIdx.y * 64;
    const int dir   = blockIdx.z;
    const int grp   = dir * 4 + blockIdx.y;

    const __nv_bfloat16* __restrict__ Wd = g_Whh[dir];
    float* __restrict__ outp = g_outd[dir];

    const int ksg = wid >> 2;               // sR half
    const int m0  = ((wid >> 1) & 1) * 32;  // warp tile (fixed per warp)
    const int n0  = (wid & 1) * 32;
    const uint32_t aQ1 = (wid < 4) ? 0u : (uint32_t)CH_ALO;  // p1 A quarter

    const int c0r = tid >> 3;
    const int c1r = (tid + 256) >> 3;
    const int c8  = (tid & 7);
    const uint32_t off0 = (uint32_t)(c0r * SROW2 + c8 * 16);
    const uint32_t off1 = (uint32_t)(c1r * SROW2 + c8 * 16);

    const int r8 = lane & 7;
    const int tI = lane >> 3;
    const uint32_t aLaneOff = (uint32_t)((r8 + (tI & 1) * 8) * SROW2 + (tI >> 1) * 16);
    const uint32_t bLaneOff = (uint32_t)((r8 + (tI >> 1) * 8) * SROW2 + (tI & 1) * 16);
    const int gid = lane >> 2;
    const int tig = lane & 3;
    const int jBase = nTile >> 2;

    float* __restrict__ sR0 = (float*)(sm + SROFF);
    float* __restrict__ sR1 = (float*)(sm + SROFF + SRBUF);
    float* __restrict__ sRme = ksg ? sR1 : sR0;

    float hreg[4] = {0.f, 0.f, 0.f, 0.f};
    float creg[4] = {0.f, 0.f, 0.f, 0.f};

    // B quarters for chunk c (step-invariant)
    auto issue_B = [&](int c) {
        const uint32_t st = sbase + (c % 3) * CSTG;
        const int bcol = c * 64;
        CPA16(st + CH_BHI + off0, Wd + (size_t)(nTile + c0r) * 1024 + bcol + c8 * 8);
        CPA16(st + CH_BHI + off1, Wd + (size_t)(nTile + c1r) * 1024 + bcol + c8 * 8);
        CPA16(st + CH_BLO + off0, Wd + (size_t)(nTile + c0r) * 1024 + 512 + bcol + c8 * 8);
        CPA16(st + CH_BLO + off1, Wd + (size_t)(nTile + c1r) * 1024 + 512 + bcol + c8 * 8);
    };

    // pre-loop: prefetch B chunks 0,1 (uncommitted; joins first A commit)
    issue_B(0); issue_B(1);

    for (int t = 0; t < LL; t++) {
        const int p2par = t & 1;
        const __nv_bfloat16* __restrict__ hhi = g_hhi[dir][p2par];
        const __nv_bfloat16* __restrict__ hlo = g_hlo[dir][p2par];
        __nv_bfloat16* __restrict__ hhin = g_hhi[dir][p2par ^ 1];
        __nv_bfloat16* __restrict__ hlon = g_hlo[dir][p2par ^ 1];

        auto issue_A = [&](int c) {
            const uint32_t st = sbase + (c % 3) * CSTG;
            const int acol = c * 64;
            CPA16(st + off0,          hhi + (size_t)(b0 + c0r) * HH + acol + c8 * 8);
            CPA16(st + off1,          hhi + (size_t)(b0 + c1r) * HH + acol + c8 * 8);
            CPA16(st + CH_ALO + off0, hlo + (size_t)(b0 + c0r) * HH + acol + c8 * 8);
            CPA16(st + CH_ALO + off1, hlo + (size_t)(b0 + c1r) * HH + acol + c8 * 8);
        };

        // prefetch G (independent of h)
        float4 gp[4];
#pragma unroll
        for (int it = 0; it < 4; it++) {
            const int idx = it * 256 + tid;
            const int bl = idx >> 4;
            const int jj = idx & 15;
            const int b  = b0 + bl;
            const int len = x_len[b];
            int tq = t;
            if (dir) { tq = len - 1 - t; if (tq < 0) tq = 0; }
            gp[it] = *(const float4*)(
                g_G + ((size_t)tq * BB + b) * GNF + dir * G4H + (size_t)(jBase + jj) * 4);
        }

        float acc[2][4][4];
#pragma unroll
        for (int i = 0; i < 2; i++)
#pragma unroll
            for (int j = 0; j < 4; j++)
#pragma unroll
                for (int q = 0; q < 4; q++) acc[i][j][q] = 0.f;

        auto compute_prod = [&](uint32_t sa, uint32_t sb) {
#pragma unroll
            for (int kk = 0; kk < 4; kk++) {
                uint32_t afr[2][4], bfr[2][4];
#pragma unroll
                for (int mi = 0; mi < 2; mi++)
                    ldmatrix_x4(afr[mi],
                                sa + (uint32_t)((m0 + mi * 16) * SROW2 + kk * 32) + aLaneOff);
#pragma unroll
                for (int nb = 0; nb < 2; nb++)
                    ldmatrix_x4(bfr[nb],
                                sb + (uint32_t)((n0 + nb * 16) * SROW2 + kk * 32) + bLaneOff);
#pragma unroll
                for (int mi = 0; mi < 2; mi++)
#pragma unroll
                    for (int ni = 0; ni < 4; ni++) {
                        const uint32_t* bp = &bfr[ni >> 1][(ni & 1) * 2];
                        mma16816(acc[mi][ni], afr[mi], bp[0], bp[1]);
                    }
            }
        };

        // post-barrier A prologue (first commit also flushes pre-issued B0,B1)
        issue_A(0); CPA_COMMIT();
        issue_A(1); CPA_COMMIT();

        for (int i = 0; i < NCH; i++) {
            asm volatile("cp.async.wait_group 1;" ::: "memory");
            __syncthreads();

            const uint32_t st = sbase + (i % 3) * CSTG;
            compute_prod(st + aQ1, st + CH_BHI);                  // P0 or P1
            const bool do2 = ((i & 1) == 0) ? (wid < 4) : (wid >= 4);
            if (do2) compute_prod(st, st + CH_BLO);               // P2 = Ahi*Blo

            if (i + 2 < NCH) { issue_A(i + 2); issue_B(i + 2); }
            CPA_COMMIT();
        }
        asm volatile("cp.async.wait_group 0;" ::: "memory");
        __syncthreads();

        // stage R through smem (stage-2 region, all reads complete)
#pragma unroll
        for (int mi = 0; mi < 2; mi++) {
            const int row = m0 + mi * 16 + gid;
#pragma unroll
            for (int ni = 0; ni < 4; ni++) {
                const int col = n0 + ni * 8 + tig * 2;
                sRme[row * 68 + col]           = acc[mi][ni][0];
                sRme[row * 68 + col + 1]       = acc[mi][ni][1];
                sRme[(row + 8) * 68 + col]     = acc[mi][ni][2];
                sRme[(row + 8) * 68 + col + 1] = acc[mi][ni][3];
            }
        }
        __syncthreads();

        // fused LSTM pointwise: h/c in registers
#pragma unroll
        for (int it = 0; it < 4; it++) {
            const int idx = it * 256 + tid;
            const int bl = idx >> 4;
            const int jj = idx & 15;
            const int b  = b0 + bl;
            const int j  = jBase + jj;
            const int len = x_len[b];
            const float4 r0 = *(const float4*)&sR0[bl * 68 + jj * 4];
            const float4 r1 = *(const float4*)&sR1[bl * 68 + jj * 4];
            float i_ = fsigmoid(r0.x + r1.x + gp[it].x);
            float f_ = fsigmoid(r0.y + r1.y + gp[it].y);
            float g_ = ftanh(r0.z + r1.z + gp[it].z);
            float o_ = fsigmoid(r0.w + r1.w + gp[it].w);
            float cn = f_ * creg[it] + i_ * g_;
            float hn = o_ * ftanh(cn);
            const bool valid = (t < len);
            if (valid) { creg[it] = cn; hreg[it] = hn; }
            const float ho = hreg[it];
            const size_t hc = (size_t)b * HH + j;
            __nv_bfloat16 hi = __float2bfloat16_rn(ho);
            hhin[hc] = hi;
            hlon[hc] = __float2bfloat16_rn(ho - __bfloat162float(hi));
            outp[((size_t)b * LL + t) * HH + j] = valid ? hn : 0.f;
        }

        // pre-barrier B prefetch for next step (uncommitted across barrier)
        if (t + 1 < LL) { issue_B(0); issue_B(1); }

        group_barrier(grp, t);
    }
}

// ---------------- attention + head ------------------------------------------
__global__ __launch_bounds__(256)
void final_kernel(const float* __restrict__ x, const int* __restrict__ x_len,
                  const float* __restrict__ target_word,
                  const float* __restrict__ W_h, const float* __restrict__ b_tanh,
                  const float* __restrict__ W_lin, const float* __restrict__ b_lin,
                  const float* __restrict__ W_out, const float* __restrict__ b_out,
                  float* __restrict__ out)
{
    __shared__ float s_u[LL];
    __shared__ float s_ctx[2 * HH];
    __shared__ float s_lin[512];
    __shared__ float s_red[8];
    __shared__ float s_twdot;

    const int b    = blockIdx.x;
    const int tid  = threadIdx.x;
    const int warp = tid >> 5;
    const int lane = tid & 31;
    const int len  = x_len[b];

    {
        float partial = 0.f;
        for (int d = tid; d < DD; d += 256) {
            float s = 0.f;
#pragma unroll
            for (int k = 0; k < 5; k++)
                s += target_word[((size_t)b * 5 + k) * DD + d];
            partial = fmaf(s * 0.2f, W_h[DD + d], partial);
        }
#pragma unroll
        for (int off = 16; off; off >>= 1)
            partial += __shfl_xor_sync(0xffffffffu, partial, off);
        if (lane == 0) s_red[warp] = partial;
        __syncthreads();
        if (tid == 0) {
            float s = 0.f;
            for (int w = 0; w < 8; w++) s += s_red[w];
            s_twdot = s;
        }
        __syncthreads();
    }
    const float twdot = s_twdot;

    for (int i = 0; i < 16; i++) {
        const int t = warp * 16 + i;
        const float* xe = x + ((size_t)b * LL + t) * DD;
        float a = 0.f;
#pragma unroll 8
        for (int q = 0; q < 32; q++) {
            int d = lane + q * 32;
            a = fmaf(xe[d], W_h[d], a);
        }
#pragma unroll
        for (int off = 16; off; off >>= 1)
            a += __shfl_xor_sync(0xffffffffu, a, off);
        if (lane == 0)
            s_u[t] = (t < len) ? (a + twdot + b_tanh[t]) : -1e6f;
    }
    __syncthreads();

    if (warp == 0) {
        float v[4];
#pragma unroll
        for (int q = 0; q < 4; q++) v[q] = s_u[lane + q * 32];
        float m = fmaxf(fmaxf(v[0], v[1]), fmaxf(v[2], v[3]));
#pragma unroll
        for (int off = 16; off; off >>= 1)
            m = fmaxf(m, __shfl_xor_sync(0xffffffffu, m, off));
        float e[4], s = 0.f;
#pragma unroll
        for (int q = 0; q < 4; q++) { e[q] = expf(v[q] - m); s += e[q]; }
#pragma unroll
        for (int off = 16; off; off >>= 1)
            s += __shfl_xor_sync(0xffffffffu, s, off);
        float inv = 1.f / s;
#pragma unroll
        for (int q = 0; q < 4; q++) s_u[lane + q * 32] = e[q] * inv;
    }
    __syncthreads();

    {
        float accj[4] = {0.f, 0.f, 0.f, 0.f};
        const float* outf = g_outd[0] + (size_t)b * LL * HH;
        const float* outb = g_outd[1] + (size_t)b * LL * HH;
        for (int t = 0; t < LL; t++) {
            const float a = s_u[t];
            int t2 = len - 1 - t;
            if (t2 < 0) t2 = 0;
#pragma unroll
            for (int q = 0; q < 4; q++) {
                const int j = tid + q * 256;
                float hv;
                if (j < HH) hv = outf[(size_t)t * HH + j];
                else        hv = outb[(size_t)t2 * HH + (j - HH)];
                accj[q] = fmaf(a, hv, accj[q]);
            }
        }
#pragma unroll
        for (int q = 0; q < 4; q++) s_ctx[tid + q * 256] = accj[q];
    }
    __syncthreads();

    for (int i = 0; i < 64; i++) {
        const int o = warp * 64 + i;
        const float* wr = W_lin + (size_t)o * (2 * HH);
        float a = 0.f;
#pragma unroll 8
        for (int q = 0; q < 32; q++) {
            int d = lane + q * 32;
            a = fmaf(s_ctx[d], wr[d], a);
        }
#pragma unroll
        for (int off = 16; off; off >>= 1)
            a += __shfl_xor_sync(0xffffffffu, a, off);
        if (lane == 0) s_lin[o] = fmaxf(a + b_lin[o], 0.f);
    }
    __syncthreads();

    if (warp == 0) {
#pragma unroll
        for (int o = 0; o < 3; o++) {
            const float* wr = W_out + (size_t)o * 512;
            float a = 0.f;
#pragma unroll
            for (int q = 0; q < 16; q++) {
                int d = lane + q * 32;
                a = fmaf(s_lin[d], wr[d], a);
            }
#pragma unroll
            for (int off = 16; off; off >>= 1)
                a += __shfl_xor_sync(0xffffffffu, a, off);
            if (lane == 0) out[b * 3 + o] = a + b_out[o];
        }
    }
}

// ---------------- launch -----------------------------------------------------
extern "C" void kernel_launch(void* const* d_in, const int* in_sizes, int n_in,
                              void* d_out, int out_size)
{
    const float* x           = (const float*)d_in[0];
    const int*   x_len       = (const int*)d_in[1];
    const float* target_word = (const float*)d_in[3];
    const float* W_ih_f      = (const float*)d_in[5];
    const float* W_hh_f      = (const float*)d_in[6];
    const float* b_f         = (const float*)d_in[7];
    const float* W_ih_b      = (const float*)d_in[8];
    const float* W_hh_b      = (const float*)d_in[9];
    const float* b_b         = (const float*)d_in[10];
    const float* W_h         = (const float*)d_in[11];
    const float* b_tanh      = (const float*)d_in[12];
    const float* W_lin       = (const float*)d_in[13];
    const float* b_lin       = (const float*)d_in[14];
    const float* W_out       = (const float*)d_in[15];
    const float* b_out       = (const float*)d_in[16];
    float* out = (float*)d_out;

    static bool attr_set = false;
    if (!attr_set) {
        cudaFuncSetAttribute(lstm_persistent,
                             cudaFuncAttributeMaxDynamicSharedMemorySize, R14_SMEM);
        cudaFuncSetAttribute(gemm_mma_kernel,
                             cudaFuncAttributeMaxDynamicSharedMemorySize, G_SMEM);
        attr_set = true;
    }

    init_hc_kernel<<<(BB * HH + 255) / 256, 256>>>();
    convert_x_kernel<<<BB * LL, 256>>>(x);
    convert_w_kernel<<<GNF, 256>>>(W_ih_f, W_ih_b, b_f, b_b);
    {
        dim3 wgrid(G4H, 2);
        convert_whh_kernel<<<wgrid, 128>>>(W_hh_f, W_hh_b);
    }

    dim3 ggrid(GNF / 256, MM_TOT / 128);   // (16, 256) = 4096 blocks
    gemm_mma_kernel<<<ggrid, 512, G_SMEM>>>();

    dim3 sgrid(G4H / 64, BB / 64, 2);      // (32, 4, 2) = 256 persistent blocks
    lstm_persistent<<<sgrid, 256, R14_SMEM>>>(x_len);

    final_kernel<<<BB, 256>>>(x, x_len, target_word, W_h, b_tanh,
                              W_lin, b_lin, W_out, b_out, out);
}

// round 15
// speedup vs baseline: 1.3513x; 1.3513x over previous
#include <cuda_runtime.h>
#include <cuda_bf16.h>
#include <math.h>
#include <stdint.h>

// Problem dims
#define BB 256
#define LL 128
#define DD 1024
#define HH 512
#define G4H 2048
#define GNF 4096
#define KS2 2048            // compact [hi|lo] storage K
#define MM_TOT (LL * BB)

// ---------------- scratch (device globals) ----------------------------------
__device__ float g_G[(size_t)MM_TOT * GNF];
__device__ float g_outd[2][(size_t)BB * LL * HH];
__device__ __nv_bfloat16 g_hhi[2][2][(size_t)BB * HH];
__device__ __nv_bfloat16 g_hlo[2][2][(size_t)BB * HH];
__device__ __nv_bfloat16 g_Xs[(size_t)MM_TOT * KS2];   // [m][ hi(1024) | lo(1024) ]
__device__ __nv_bfloat16 g_Ws[(size_t)GNF * KS2];      // [c][ hi(1024) | lo(1024) ]
__device__ __nv_bfloat16 g_Whh[2][(size_t)G4H * 1024];
__device__ float g_bias[GNF];

struct GrpBar { unsigned int cnt; unsigned int gen; unsigned int pad[62]; };
__device__ GrpBar g_bars[8];

// ---------------- helpers ----------------------------------------------------
__device__ __forceinline__ uint32_t smem_u32(const void* p) {
    uint32_t a;
    asm("{ .reg .u64 t; cvta.to.shared.u64 t, %1; cvt.u32.u64 %0, t; }"
        : "=r"(a) : "l"(p));
    return a;
}
#define CPA16(dst, src) \
    asm volatile("cp.async.ca.shared.global [%0], [%1], 16;" :: "r"(dst), "l"(src))
#define CPA_COMMIT() asm volatile("cp.async.commit_group;" ::: "memory")

__device__ __forceinline__ void ldmatrix_x4(uint32_t* r, uint32_t addr) {
    asm volatile("ldmatrix.sync.aligned.m8n8.x4.shared.b16 {%0,%1,%2,%3}, [%4];"
                 : "=r"(r[0]), "=r"(r[1]), "=r"(r[2]), "=r"(r[3]) : "r"(addr));
}
__device__ __forceinline__ void mma16816(float* c, const uint32_t* a,
                                         uint32_t b0, uint32_t b1) {
    asm volatile(
        "mma.sync.aligned.m16n8k16.row.col.f32.bf16.bf16.f32 "
        "{%0,%1,%2,%3}, {%4,%5,%6,%7}, {%8,%9}, {%0,%1,%2,%3};"
        : "+f"(c[0]), "+f"(c[1]), "+f"(c[2]), "+f"(c[3])
        : "r"(a[0]), "r"(a[1]), "r"(a[2]), "r"(a[3]), "r"(b0), "r"(b1));
}
__device__ __forceinline__ float fsigmoid(float x) {
    return __fdividef(1.f, 1.f + __expf(-x));
}
__device__ __forceinline__ float ftanh(float x) {
    float e2 = __expf(2.f * x);
    return __fdividef(e2 - 1.f, e2 + 1.f);
}

__device__ __forceinline__ void group_barrier(int gid, int step) {
    __syncthreads();
    if (threadIdx.x == 0) {
        __threadfence();
        unsigned int a = atomicAdd(&g_bars[gid].cnt, 1u);
        if (a == 31u) {
            g_bars[gid].cnt = 0;
            __threadfence();
            atomicExch(&g_bars[gid].gen, (unsigned)(step + 1));
        } else {
            unsigned int g;
            do {
                asm volatile("ld.acquire.gpu.u32 %0, [%1];"
                             : "=r"(g) : "l"(&g_bars[gid].gen));
                if (g > (unsigned)step) break;
                __nanosleep(32);
            } while (true);
        }
    }
    __syncthreads();
}

// ---------------- init -------------------------------------------------------
__global__ void init_hc_kernel() {
    int i = blockIdx.x * blockDim.x + threadIdx.x;
    if (i < 8) { g_bars[i].cnt = 0; g_bars[i].gen = 0; }
    if (i < BB * HH) {
        g_hhi[0][0][i] = __float2bfloat16_rn(0.f);
        g_hhi[1][0][i] = __float2bfloat16_rn(0.f);
        g_hlo[0][0][i] = __float2bfloat16_rn(0.f);
        g_hlo[1][0][i] = __float2bfloat16_rn(0.f);
    }
}

// ---------------- fp32 -> bf16 hi/lo split converters ------------------------
__global__ __launch_bounds__(256)
void convert_x_kernel(const float* __restrict__ X) {
    const int bt = blockIdx.x;
    const int b = bt >> 7;
    const int t = bt & 127;
    const float4 v = ((const float4*)(X + (size_t)bt * DD))[threadIdx.x];
    __nv_bfloat16 hi4[4], lo4[4];
    hi4[0] = __float2bfloat16_rn(v.x); lo4[0] = __float2bfloat16_rn(v.x - __bfloat162float(hi4[0]));
    hi4[1] = __float2bfloat16_rn(v.y); lo4[1] = __float2bfloat16_rn(v.y - __bfloat162float(hi4[1]));
    hi4[2] = __float2bfloat16_rn(v.z); lo4[2] = __float2bfloat16_rn(v.z - __bfloat162float(hi4[2]));
    hi4[3] = __float2bfloat16_rn(v.w); lo4[3] = __float2bfloat16_rn(v.w - __bfloat162float(hi4[3]));
    const size_t base = ((size_t)t * BB + b) * KS2 + threadIdx.x * 4;
    *(uint2*)&g_Xs[base]      = *(const uint2*)hi4;
    *(uint2*)&g_Xs[base + DD] = *(const uint2*)lo4;
}

__global__ __launch_bounds__(256)
void convert_w_kernel(const float* __restrict__ Wf, const float* __restrict__ Wb,
                      const float* __restrict__ bf, const float* __restrict__ bb) {
    const int c = blockIdx.x;
    const int dir = (c >= G4H);
    const int local = c - dir * G4H;
    const int j = local >> 2, gate = local & 3;
    const int srow = gate * HH + j;
    const float* src = dir ? (Wb + (size_t)srow * DD) : (Wf + (size_t)srow * DD);
    const float4 v = ((const float4*)src)[threadIdx.x];
    __nv_bfloat16 hi4[4], lo4[4];
    hi4[0] = __float2bfloat16_rn(v.x); lo4[0] = __float2bfloat16_rn(v.x - __bfloat162float(hi4[0]));
    hi4[1] = __float2bfloat16_rn(v.y); lo4[1] = __float2bfloat16_rn(v.y - __bfloat162float(hi4[1]));
    hi4[2] = __float2bfloat16_rn(v.z); lo4[2] = __float2bfloat16_rn(v.z - __bfloat162float(hi4[2]));
    hi4[3] = __float2bfloat16_rn(v.w); lo4[3] = __float2bfloat16_rn(v.w - __bfloat162float(hi4[3]));
    const size_t base = (size_t)c * KS2 + threadIdx.x * 4;
    *(uint2*)&g_Ws[base]      = *(const uint2*)hi4;
    *(uint2*)&g_Ws[base + DD] = *(const uint2*)lo4;
    if (threadIdx.x == 0)
        g_bias[c] = dir ? bb[srow] : bf[srow];
}

__global__ __launch_bounds__(128)
void convert_whh_kernel(const float* __restrict__ Wf, const float* __restrict__ Wb) {
    const int c   = blockIdx.x;
    const int dir = blockIdx.y;
    const int gate = c & 3, j = c >> 2;
    const float* __restrict__ W = dir ? Wb : Wf;
    const float4 v = ((const float4*)(W + (size_t)(gate * HH + j) * HH))[threadIdx.x];
    __nv_bfloat16 hi4[4], lo4[4];
    hi4[0] = __float2bfloat16_rn(v.x); lo4[0] = __float2bfloat16_rn(v.x - __bfloat162float(hi4[0]));
    hi4[1] = __float2bfloat16_rn(v.y); lo4[1] = __float2bfloat16_rn(v.y - __bfloat162float(hi4[1]));
    hi4[2] = __float2bfloat16_rn(v.z); lo4[2] = __float2bfloat16_rn(v.z - __bfloat162float(hi4[2]));
    hi4[3] = __float2bfloat16_rn(v.w); lo4[3] = __float2bfloat16_rn(v.w - __bfloat162float(hi4[3]));
    __nv_bfloat16* dst = &g_Whh[dir][(size_t)c * 1024];
    *(uint2*)&dst[threadIdx.x * 4]       = *(const uint2*)hi4;
    *(uint2*)&dst[512 + threadIdx.x * 4] = *(const uint2*)lo4;
}

// ---------------- input-projection GEMM: 128x256 tile, 512 thr, 3-stage ------
// Logical K = 3072 (48 kt of 64): seg0 = A.hi x B.hi, seg1 = A.lo x B.hi,
// seg2 = A.hi x B.lo  (reads remapped into the compact [hi|lo] arrays).
#define SROW2 144
#define GA_TILE (128 * SROW2)        // 18432
#define GB_TILE (256 * SROW2)        // 36864
#define GSTG (GA_TILE + GB_TILE)     // 55296
#define G_SMEM (3 * GSTG)            // 165888
#define GKT 48

__global__ __launch_bounds__(512, 1)
void gemm_mma_kernel() {
    extern __shared__ __align__(16) char sm[];
    const uint32_t sbase = smem_u32(sm);

    const int tid  = threadIdx.x;
    const int wid  = tid >> 5;
    const int lane = tid & 31;
    const int nTile = blockIdx.x * 256;
    const int mTile = blockIdx.y * 128;

    // 16 warps: 2 m-halves x 8 n-strips, warp tile 64x32
    const int m0 = (wid & 1) * 64;
    const int n0 = (wid >> 1) * 32;

    // load mapping: A 1024 chunks (2/thread), B 2048 chunks (4/thread)
    const int lc8 = tid & 7;
    const int lr  = tid >> 3;            // 0..63
    const uint32_t aoff0 = (uint32_t)(lr * SROW2 + lc8 * 16);
    const uint32_t aoff1 = (uint32_t)((lr + 64) * SROW2 + lc8 * 16);
    const __nv_bfloat16* __restrict__ gA = g_Xs + (size_t)mTile * KS2;
    const __nv_bfloat16* __restrict__ gB = g_Ws + (size_t)nTile * KS2;

    auto issue_stage = [&](int kt) {
        const uint32_t sa = sbase + (kt % 3) * GSTG;
        const uint32_t sb = sa + GA_TILE;
        const int seg = kt >> 4;
        const int k64 = (kt & 15) * 64;
        const size_t acol = (size_t)((seg == 1) ? (DD + k64) : k64) + lc8 * 8;
        const size_t bcol = (size_t)((seg == 2) ? (DD + k64) : k64) + lc8 * 8;
        // A: rows lr and lr+64
        CPA16(sa + aoff0, gA + (size_t)lr * KS2 + acol);
        CPA16(sa + aoff1, gA + (size_t)(lr + 64) * KS2 + acol);
        // B: rows lr, lr+64, lr+128, lr+192
#pragma unroll
        for (int q = 0; q < 4; q++) {
            const int row = lr + q * 64;
            CPA16(sb + aoff0 + (uint32_t)(q * 64 * SROW2),
                  gB + (size_t)row * KS2 + bcol);
        }
    };

    float acc[4][4][4];
#pragma unroll
    for (int i = 0; i < 4; i++)
#pragma unroll
        for (int j = 0; j < 4; j++)
#pragma unroll
            for (int q = 0; q < 4; q++) acc[i][j][q] = 0.f;

    const int r8 = lane & 7;
    const int tI = lane >> 3;
    const uint32_t aLaneOff = (uint32_t)((r8 + (tI & 1) * 8) * SROW2 + (tI >> 1) * 16);
    const uint32_t bLaneOff = (uint32_t)((r8 + (tI >> 1) * 8) * SROW2 + (tI & 1) * 16);

    issue_stage(0); CPA_COMMIT();
    issue_stage(1); CPA_COMMIT();

    for (int kt = 0; kt < GKT; kt++) {
        asm volatile("cp.async.wait_group 1;" ::: "memory");
        __syncthreads();

        const uint32_t sa = sbase + (kt % 3) * GSTG;
        const uint32_t sb = sa + GA_TILE;
#pragma unroll
        for (int kk = 0; kk < 4; kk++) {
            uint32_t afr[4][4], bfr[2][4];
#pragma unroll
            for (int mi = 0; mi < 4; mi++)
                ldmatrix_x4(afr[mi],
                            sa + (uint32_t)((m0 + mi * 16) * SROW2 + kk * 32) + aLaneOff);
#pragma unroll
            for (int nb = 0; nb < 2; nb++)
                ldmatrix_x4(bfr[nb],
                            sb + (uint32_t)((n0 + nb * 16) * SROW2 + kk * 32) + bLaneOff);
#pragma unroll
            for (int mi = 0; mi < 4; mi++)
#pragma unroll
                for (int ni = 0; ni < 4; ni++) {
                    const uint32_t* bp = &bfr[ni >> 1][(ni & 1) * 2];
                    mma16816(acc[mi][ni], afr[mi], bp[0], bp[1]);
                }
        }
        if (kt + 2 < GKT) issue_stage(kt + 2);
        CPA_COMMIT();
    }

    const int gid = lane >> 2;
    const int tig = lane & 3;
#pragma unroll
    for (int mi = 0; mi < 4; mi++) {
        const int m = mTile + m0 + mi * 16 + gid;
#pragma unroll
        for (int ni = 0; ni < 4; ni++) {
            const int n = nTile + n0 + ni * 8 + tig * 2;
            const float2 bv = *(const float2*)&g_bias[n];
            float2 o0 = make_float2(acc[mi][ni][0] + bv.x, acc[mi][ni][1] + bv.y);
            float2 o1 = make_float2(acc[mi][ni][2] + bv.x, acc[mi][ni][3] + bv.y);
            *(float2*)&g_G[(size_t)m * GNF + n]       = o0;
            *(float2*)&g_G[(size_t)(m + 8) * GNF + n] = o1;
        }
    }
}

// ---------------- persistent recurrence (R13/R12 winner) ---------------------
#define ST_A (64 * SROW2)
#define ST_B (64 * SROW2)
#define STG  (ST_A + ST_B)
#define NST 6
#define R12_SMEM (NST * STG)
#define NPAIR 12
#define SRBUF (64 * 68 * 4)
#define SROFF (4 * STG)

__global__ __launch_bounds__(256, 2)
void lstm_persistent(const int* __restrict__ x_len)
{
    extern __shared__ __align__(16) char sm[];
    const uint32_t sbase = smem_u32(sm);

    const int tid  = threadIdx.x;
    const int wid  = tid >> 5;
    const int lane = tid & 31;
    const int nTile = blockIdx.x * 64;
    const int b0    = blockIdx.y * 64;
    const int dir   = blockIdx.z;
    const int grp   = dir * 4 + blockIdx.y;

    const __nv_bfloat16* __restrict__ Wd = g_Whh[dir];
    float* __restrict__ outp = g_outd[dir];

    const int ksg = wid >> 2;
    const int w4  = wid & 3;
    const int m0  = (w4 & 1) * 32;
    const int n0  = (w4 >> 1) * 32;

    const int c0r = tid >> 3;
    const int c1r = (tid + 256) >> 3;
    const int c8  = (tid & 7);
    const uint32_t off0 = (uint32_t)(c0r * SROW2 + c8 * 16);
    const uint32_t off1 = (uint32_t)(c1r * SROW2 + c8 * 16);

    const int r8 = lane & 7;
    const int tI = lane >> 3;
    const uint32_t aLaneOff = (uint32_t)((r8 + (tI & 1) * 8) * SROW2 + (tI >> 1) * 16);
    const uint32_t bLaneOff = (uint32_t)((r8 + (tI >> 1) * 8) * SROW2 + (tI & 1) * 16);
    const int gid = lane >> 2;
    const int tig = lane & 3;
    const int jBase = nTile >> 2;

    float* __restrict__ sR0 = (float*)(sm + SROFF);
    float* __restrict__ sR1 = (float*)(sm + SROFF + SRBUF);
    float* __restrict__ sRme = ksg ? sR1 : sR0;

    float hreg[4] = {0.f, 0.f, 0.f, 0.f};
    float creg[4] = {0.f, 0.f, 0.f, 0.f};

    auto issue_B = [&](int kt) {
        const int stage = kt % NST;
        const int seg  = kt >> 3;
        const int ktk  = kt & 7;
        const int bcol = (seg == 2) ? (512 + ktk * 64) : (ktk * 64);
        const uint32_t sb = sbase + stage * STG + ST_A;
        CPA16(sb + off0, Wd + (size_t)(nTile + c0r) * 1024 + bcol + c8 * 8);
        CPA16(sb + off1, Wd + (size_t)(nTile + c1r) * 1024 + bcol + c8 * 8);
    };

    issue_B(0); issue_B(1); issue_B(2); issue_B(3); CPA_COMMIT();

    for (int t = 0; t < LL; t++) {
        const int p2 = t & 1;
        const __nv_bfloat16* __restrict__ hhi = g_hhi[dir][p2];
        const __nv_bfloat16* __restrict__ hlo = g_hlo[dir][p2];
        __nv_bfloat16* __restrict__ hhin = g_hhi[dir][p2 ^ 1];
        __nv_bfloat16* __restrict__ hlon = g_hlo[dir][p2 ^ 1];

        auto issue_A = [&](int kt) {
            const int stage = kt % NST;
            const int seg  = kt >> 3;
            const int acol = (kt & 7) * 64;
            const __nv_bfloat16* __restrict__ hsrc = (seg == 1) ? hlo : hhi;
            const uint32_t sa = sbase + stage * STG;
            CPA16(sa + off0, hsrc + (size_t)(b0 + c0r) * HH + acol + c8 * 8);
            CPA16(sa + off1, hsrc + (size_t)(b0 + c1r) * HH + acol + c8 * 8);
        };
        auto issue_AB = [&](int kt) { issue_A(kt); issue_B(kt); };

        float4 gp[4];
#pragma unroll
        for (int it = 0; it < 4; it++) {
            const int idx = it * 256 + tid;
            const int bl = idx >> 4;
            const int jj = idx & 15;
            const int b  = b0 + bl;
            const int len = x_len[b];
            int tq = t;
            if (dir) { tq = len - 1 - t; if (tq < 0) tq = 0; }
            gp[it] = *(const float4*)(
                g_G + ((size_t)tq * BB + b) * GNF + dir * G4H + (size_t)(jBase + jj) * 4);
        }

        float acc[2][4][4];
#pragma unroll
        for (int i = 0; i < 2; i++)
#pragma unroll
            for (int j = 0; j < 4; j++)
#pragma unroll
                for (int q = 0; q < 4; q++) acc[i][j][q] = 0.f;

        issue_A(0); issue_A(1); CPA_COMMIT();
        issue_A(2); issue_A(3); CPA_COMMIT();

        for (int p = 0; p < NPAIR; p++) {
            asm volatile("cp.async.wait_group 1;" ::: "memory");
            __syncthreads();

            const int kt = 2 * p + ksg;
            const uint32_t sa = sbase + (kt % NST) * STG;
            const uint32_t sb = sa + ST_A;
#pragma unroll
            for (int kk = 0; kk < 4; kk++) {
                uint32_t afr[2][4], bfr[2][4];
#pragma unroll
                for (int mi = 0; mi < 2; mi++)
                    ldmatrix_x4(afr[mi],
                                sa + (uint32_t)((m0 + mi * 16) * SROW2 + kk * 32) + aLaneOff);
#pragma unroll
                for (int nb = 0; nb < 2; nb++)
                    ldmatrix_x4(bfr[nb],
                                sb + (uint32_t)((n0 + nb * 16) * SROW2 + kk * 32) + bLaneOff);
#pragma unroll
                for (int mi = 0; mi < 2; mi++)
#pragma unroll
                    for (int ni = 0; ni < 4; ni++) {
                        const uint32_t* bp = &bfr[ni >> 1][(ni & 1) * 2];
                        mma16816(acc[mi][ni], afr[mi], bp[0], bp[1]);
                    }
            }
            if (p + 2 < NPAIR) { issue_AB(2 * p + 4); issue_AB(2 * p + 5); }
            CPA_COMMIT();
        }
        asm volatile("cp.async.wait_group 0;" ::: "memory");
        __syncthreads();

#pragma unroll
        for (int mi = 0; mi < 2; mi++) {
            const int row = m0 + mi * 16 + gid;
#pragma unroll
            for (int ni = 0; ni < 4; ni++) {
                const int col = n0 + ni * 8 + tig * 2;
                sRme[row * 68 + col]           = acc[mi][ni][0];
                sRme[row * 68 + col + 1]       = acc[mi][ni][1];
                sRme[(row + 8) * 68 + col]     = acc[mi][ni][2];
                sRme[(row + 8) * 68 + col + 1] = acc[mi][ni][3];
            }
        }
        __syncthreads();

#pragma unroll
        for (int it = 0; it < 4; it++) {
            const int idx = it * 256 + tid;
            const int bl = idx >> 4;
            const int jj = idx & 15;
            const int b  = b0 + bl;
            const int j  = jBase + jj;
            const int len = x_len[b];
            const float4 r0 = *(const float4*)&sR0[bl * 68 + jj * 4];
            const float4 r1 = *(const float4*)&sR1[bl * 68 + jj * 4];
            float i_ = fsigmoid(r0.x + r1.x + gp[it].x);
            float f_ = fsigmoid(r0.y + r1.y + gp[it].y);
            float g_ = ftanh(r0.z + r1.z + gp[it].z);
            float o_ = fsigmoid(r0.w + r1.w + gp[it].w);
            float cn = f_ * creg[it] + i_ * g_;
            float hn = o_ * ftanh(cn);
            const bool valid = (t < len);
            if (valid) { creg[it] = cn; hreg[it] = hn; }
            const float ho = hreg[it];
            const size_t hc = (size_t)b * HH + j;
            __nv_bfloat16 hi = __float2bfloat16_rn(ho);
            hhin[hc] = hi;
            hlon[hc] = __float2bfloat16_rn(ho - __bfloat162float(hi));
            outp[((size_t)b * LL + t) * HH + j] = valid ? hn : 0.f;
        }

        if (t + 1 < LL) {
            issue_B(0); issue_B(1); issue_B(2); issue_B(3);
        }
        CPA_COMMIT();

        group_barrier(grp, t);
    }
}

// ---------------- attention + head ------------------------------------------
__global__ __launch_bounds__(256)
void final_kernel(const float* __restrict__ x, const int* __restrict__ x_len,
                  const float* __restrict__ target_word,
                  const float* __restrict__ W_h, const float* __restrict__ b_tanh,
                  const float* __restrict__ W_lin, const float* __restrict__ b_lin,
                  const float* __restrict__ W_out, const float* __restrict__ b_out,
                  float* __restrict__ out)
{
    __shared__ float s_u[LL];
    __shared__ float s_ctx[2 * HH];
    __shared__ float s_lin[512];
    __shared__ float s_red[8];
    __shared__ float s_twdot;

    const int b    = blockIdx.x;
    const int tid  = threadIdx.x;
    const int warp = tid >> 5;
    const int lane = tid & 31;
    const int len  = x_len[b];

    {
        float partial = 0.f;
        for (int d = tid; d < DD; d += 256) {
            float s = 0.f;
#pragma unroll
            for (int k = 0; k < 5; k++)
                s += target_word[((size_t)b * 5 + k) * DD + d];
            partial = fmaf(s * 0.2f, W_h[DD + d], partial);
        }
#pragma unroll
        for (int off = 16; off; off >>= 1)
            partial += __shfl_xor_sync(0xffffffffu, partial, off);
        if (lane == 0) s_red[warp] = partial;
        __syncthreads();
        if (tid == 0) {
            float s = 0.f;
            for (int w = 0; w < 8; w++) s += s_red[w];
            s_twdot = s;
        }
        __syncthreads();
    }
    const float twdot = s_twdot;

    for (int i = 0; i < 16; i++) {
        const int t = warp * 16 + i;
        const float* xe = x + ((size_t)b * LL + t) * DD;
        float a = 0.f;
#pragma unroll 8
        for (int q = 0; q < 32; q++) {
            int d = lane + q * 32;
            a = fmaf(xe[d], W_h[d], a);
        }
#pragma unroll
        for (int off = 16; off; off >>= 1)
            a += __shfl_xor_sync(0xffffffffu, a, off);
        if (lane == 0)
            s_u[t] = (t < len) ? (a + twdot + b_tanh[t]) : -1e6f;
    }
    __syncthreads();

    if (warp == 0) {
        float v[4];
#pragma unroll
        for (int q = 0; q < 4; q++) v[q] = s_u[lane + q * 32];
        float m = fmaxf(fmaxf(v[0], v[1]), fmaxf(v[2], v[3]));
#pragma unroll
        for (int off = 16; off; off >>= 1)
            m = fmaxf(m, __shfl_xor_sync(0xffffffffu, m, off));
        float e[4], s = 0.f;
#pragma unroll
        for (int q = 0; q < 4; q++) { e[q] = expf(v[q] - m); s += e[q]; }
#pragma unroll
        for (int off = 16; off; off >>= 1)
            s += __shfl_xor_sync(0xffffffffu, s, off);
        float inv = 1.f / s;
#pragma unroll
        for (int q = 0; q < 4; q++) s_u[lane + q * 32] = e[q] * inv;
    }
    __syncthreads();

    {
        float accj[4] = {0.f, 0.f, 0.f, 0.f};
        const float* outf = g_outd[0] + (size_t)b * LL * HH;
        const float* outb = g_outd[1] + (size_t)b * LL * HH;
        for (int t = 0; t < LL; t++) {
            const float a = s_u[t];
            int t2 = len - 1 - t;
            if (t2 < 0) t2 = 0;
#pragma unroll
            for (int q = 0; q < 4; q++) {
                const int j = tid + q * 256;
                float hv;
                if (j < HH) hv = outf[(size_t)t * HH + j];
                else        hv = outb[(size_t)t2 * HH + (j - HH)];
                accj[q] = fmaf(a, hv, accj[q]);
            }
        }
#pragma unroll
        for (int q = 0; q < 4; q++) s_ctx[tid + q * 256] = accj[q];
    }
    __syncthreads();

    for (int i = 0; i < 64; i++) {
        const int o = warp * 64 + i;
        const float* wr = W_lin + (size_t)o * (2 * HH);
        float a = 0.f;
#pragma unroll 8
        for (int q = 0; q < 32; q++) {
            int d = lane + q * 32;
            a = fmaf(s_ctx[d], wr[d], a);
        }
#pragma unroll
        for (int off = 16; off; off >>= 1)
            a += __shfl_xor_sync(0xffffffffu, a, off);
        if (lane == 0) s_lin[o] = fmaxf(a + b_lin[o], 0.f);
    }
    __syncthreads();

    if (warp == 0) {
#pragma unroll
        for (int o = 0; o < 3; o++) {
            const float* wr = W_out + (size_t)o * 512;
            float a = 0.f;
#pragma unroll
            for (int q = 0; q < 16; q++) {
                int d = lane + q * 32;
                a = fmaf(s_lin[d], wr[d], a);
            }
#pragma unroll
            for (int off = 16; off; off >>= 1)
                a += __shfl_xor_sync(0xffffffffu, a, off);
            if (lane == 0) out[b * 3 + o] = a + b_out[o];
        }
    }
}

// ---------------- launch -----------------------------------------------------
extern "C" void kernel_launch(void* const* d_in, const int* in_sizes, int n_in,
                              void* d_out, int out_size)
{
    const float* x           = (const float*)d_in[0];
    const int*   x_len       = (const int*)d_in[1];
    const float* target_word = (const float*)d_in[3];
    const float* W_ih_f      = (const float*)d_in[5];
    const float* W_hh_f      = (const float*)d_in[6];
    const float* b_f         = (const float*)d_in[7];
    const float* W_ih_b      = (const float*)d_in[8];
    const float* W_hh_b      = (const float*)d_in[9];
    const float* b_b         = (const float*)d_in[10];
    const float* W_h         = (const float*)d_in[11];
    const float* b_tanh      = (const float*)d_in[12];
    const float* W_lin       = (const float*)d_in[13];
    const float* b_lin       = (const float*)d_in[14];
    const float* W_out       = (const float*)d_in[15];
    const float* b_out       = (const float*)d_in[16];
    float* out = (float*)d_out;

    static bool attr_set = false;
    if (!attr_set) {
        cudaFuncSetAttribute(lstm_persistent,
                             cudaFuncAttributeMaxDynamicSharedMemorySize, R12_SMEM);
        cudaFuncSetAttribute(gemm_mma_kernel,
                             cudaFuncAttributeMaxDynamicSharedMemorySize, G_SMEM);
        attr_set = true;
    }

    init_hc_kernel<<<(BB * HH + 255) / 256, 256>>>();
    convert_x_kernel<<<BB * LL, 256>>>(x);
    convert_w_kernel<<<GNF, 256>>>(W_ih_f, W_ih_b, b_f, b_b);
    {
        dim3 wgrid(G4H, 2);
        convert_whh_kernel<<<wgrid, 128>>>(W_hh_f, W_hh_b);
    }

    dim3 ggrid(GNF / 256, MM_TOT / 128);   // (16, 256) = 4096 blocks
    gemm_mma_kernel<<<ggrid, 512, G_SMEM>>>();

    dim3 sgrid(G4H / 64, BB / 64, 2);      // (32, 4, 2) = 256 persistent blocks
    lstm_persistent<<<sgrid, 256, R12_SMEM>>>(x_len);

    final_kernel<<<BB, 256>>>(x, x_len, target_word, W_h, b_tanh,
                              W_lin, b_lin, W_out, b_out, out);
}

// round 16
// speedup vs baseline: 1.5606x; 1.1548x over previous
#include <cuda_runtime.h>
#include <cuda_bf16.h>
#include <cuda_fp16.h>
#include <math.h>
#include <stdint.h>

// Problem dims
#define BB 256
#define LL 128
#define DD 1024
#define HH 512
#define G4H 2048
#define GNF 4096
#define KS2 2048            // compact [hi|lo] storage K
#define MM_TOT (LL * BB)

// ---------------- scratch (device globals) ----------------------------------
__device__ float g_G[(size_t)MM_TOT * GNF];
__device__ float g_outd[2][(size_t)BB * LL * HH];
__device__ __nv_bfloat16 g_hhi[2][2][(size_t)BB * HH];
__device__ __nv_bfloat16 g_hlo[2][2][(size_t)BB * HH];
__device__ __half g_Xs[(size_t)MM_TOT * KS2];   // [m][ hi(1024) | lo(1024) ] fp16
__device__ __half g_Ws[(size_t)GNF * KS2];      // [c][ hi(1024) | lo(1024) ] fp16
__device__ __nv_bfloat16 g_Whh[2][(size_t)G4H * 1024];
__device__ float g_bias[GNF];

struct GrpBar { unsigned int cnt; unsigned int gen; unsigned int pad[62]; };
__device__ GrpBar g_bars[8];

// ---------------- helpers ----------------------------------------------------
__device__ __forceinline__ uint32_t smem_u32(const void* p) {
    uint32_t a;
    asm("{ .reg .u64 t; cvta.to.shared.u64 t, %1; cvt.u32.u64 %0, t; }"
        : "=r"(a) : "l"(p));
    return a;
}
#define CPA16(dst, src) \
    asm volatile("cp.async.ca.shared.global [%0], [%1], 16;" :: "r"(dst), "l"(src))
#define CPA_COMMIT() asm volatile("cp.async.commit_group;" ::: "memory")

__device__ __forceinline__ void ldmatrix_x4(uint32_t* r, uint32_t addr) {
    asm volatile("ldmatrix.sync.aligned.m8n8.x4.shared.b16 {%0,%1,%2,%3}, [%4];"
                 : "=r"(r[0]), "=r"(r[1]), "=r"(r[2]), "=r"(r[3]) : "r"(addr));
}
// bf16 mma (recurrence)
__device__ __forceinline__ void mma16816(float* c, const uint32_t* a,
                                         uint32_t b0, uint32_t b1) {
    asm volatile(
        "mma.sync.aligned.m16n8k16.row.col.f32.bf16.bf16.f32 "
        "{%0,%1,%2,%3}, {%4,%5,%6,%7}, {%8,%9}, {%0,%1,%2,%3};"
        : "+f"(c[0]), "+f"(c[1]), "+f"(c[2]), "+f"(c[3])
        : "r"(a[0]), "r"(a[1]), "r"(a[2]), "r"(a[3]), "r"(b0), "r"(b1));
}
// fp16 mma (input GEMM)
__device__ __forceinline__ void mma16816h(float* c, const uint32_t* a,
                                          uint32_t b0, uint32_t b1) {
    asm volatile(
        "mma.sync.aligned.m16n8k16.row.col.f32.f16.f16.f32 "
        "{%0,%1,%2,%3}, {%4,%5,%6,%7}, {%8,%9}, {%0,%1,%2,%3};"
        : "+f"(c[0]), "+f"(c[1]), "+f"(c[2]), "+f"(c[3])
        : "r"(a[0]), "r"(a[1]), "r"(a[2]), "r"(a[3]), "r"(b0), "r"(b1));
}
__device__ __forceinline__ float fsigmoid(float x) {
    return __fdividef(1.f, 1.f + __expf(-x));
}
__device__ __forceinline__ float ftanh(float x) {
    float e2 = __expf(2.f * x);
    return __fdividef(e2 - 1.f, e2 + 1.f);
}

__device__ __forceinline__ void group_barrier(int gid, int step) {
    __syncthreads();
    if (threadIdx.x == 0) {
        __threadfence();
        unsigned int a = atomicAdd(&g_bars[gid].cnt, 1u);
        if (a == 31u) {
            g_bars[gid].cnt = 0;
            __threadfence();
            atomicExch(&g_bars[gid].gen, (unsigned)(step + 1));
        } else {
            unsigned int g;
            do {
                asm volatile("ld.acquire.gpu.u32 %0, [%1];"
                             : "=r"(g) : "l"(&g_bars[gid].gen));
                if (g > (unsigned)step) break;
                __nanosleep(32);
            } while (true);
        }
    }
    __syncthreads();
}

// ---------------- init -------------------------------------------------------
__global__ void init_hc_kernel() {
    int i = blockIdx.x * blockDim.x + threadIdx.x;
    if (i < 8) { g_bars[i].cnt = 0; g_bars[i].gen = 0; }
    if (i < BB * HH) {
        g_hhi[0][0][i] = __float2bfloat16_rn(0.f);
        g_hhi[1][0][i] = __float2bfloat16_rn(0.f);
        g_hlo[0][0][i] = __float2bfloat16_rn(0.f);
        g_hlo[1][0][i] = __float2bfloat16_rn(0.f);
    }
}

// ---------------- fp32 -> fp16 hi/lo split converters (input GEMM) -----------
__global__ __launch_bounds__(256)
void convert_x_kernel(const float* __restrict__ X) {
    const int bt = blockIdx.x;
    const int b = bt >> 7;
    const int t = bt & 127;
    const float4 v = ((const float4*)(X + (size_t)bt * DD))[threadIdx.x];
    __half hi4[4], lo4[4];
    hi4[0] = __float2half_rn(v.x); lo4[0] = __float2half_rn(v.x - __half2float(hi4[0]));
    hi4[1] = __float2half_rn(v.y); lo4[1] = __float2half_rn(v.y - __half2float(hi4[1]));
    hi4[2] = __float2half_rn(v.z); lo4[2] = __float2half_rn(v.z - __half2float(hi4[2]));
    hi4[3] = __float2half_rn(v.w); lo4[3] = __float2half_rn(v.w - __half2float(hi4[3]));
    const size_t base = ((size_t)t * BB + b) * KS2 + threadIdx.x * 4;
    *(uint2*)&g_Xs[base]      = *(const uint2*)hi4;
    *(uint2*)&g_Xs[base + DD] = *(const uint2*)lo4;
}

__global__ __launch_bounds__(256)
void convert_w_kernel(const float* __restrict__ Wf, const float* __restrict__ Wb,
                      const float* __restrict__ bf, const float* __restrict__ bb) {
    const int c = blockIdx.x;
    const int dir = (c >= G4H);
    const int local = c - dir * G4H;
    const int j = local >> 2, gate = local & 3;
    const int srow = gate * HH + j;
    const float* src = dir ? (Wb + (size_t)srow * DD) : (Wf + (size_t)srow * DD);
    const float4 v = ((const float4*)src)[threadIdx.x];
    __half hi4[4], lo4[4];
    hi4[0] = __float2half_rn(v.x); lo4[0] = __float2half_rn(v.x - __half2float(hi4[0]));
    hi4[1] = __float2half_rn(v.y); lo4[1] = __float2half_rn(v.y - __half2float(hi4[1]));
    hi4[2] = __float2half_rn(v.z); lo4[2] = __float2half_rn(v.z - __half2float(hi4[2]));
    hi4[3] = __float2half_rn(v.w); lo4[3] = __float2half_rn(v.w - __half2float(hi4[3]));
    const size_t base = (size_t)c * KS2 + threadIdx.x * 4;
    *(uint2*)&g_Ws[base]      = *(const uint2*)hi4;
    *(uint2*)&g_Ws[base + DD] = *(const uint2*)lo4;
    if (threadIdx.x == 0)
        g_bias[c] = dir ? bb[srow] : bf[srow];
}

__global__ __launch_bounds__(128)
void convert_whh_kernel(const float* __restrict__ Wf, const float* __restrict__ Wb) {
    const int c   = blockIdx.x;
    const int dir = blockIdx.y;
    const int gate = c & 3, j = c >> 2;
    const float* __restrict__ W = dir ? Wb : Wf;
    const float4 v = ((const float4*)(W + (size_t)(gate * HH + j) * HH))[threadIdx.x];
    __nv_bfloat16 hi4[4], lo4[4];
    hi4[0] = __float2bfloat16_rn(v.x); lo4[0] = __float2bfloat16_rn(v.x - __bfloat162float(hi4[0]));
    hi4[1] = __float2bfloat16_rn(v.y); lo4[1] = __float2bfloat16_rn(v.y - __bfloat162float(hi4[1]));
    hi4[2] = __float2bfloat16_rn(v.z); lo4[2] = __float2bfloat16_rn(v.z - __bfloat162float(hi4[2]));
    hi4[3] = __float2bfloat16_rn(v.w); lo4[3] = __float2bfloat16_rn(v.w - __bfloat162float(hi4[3]));
    __nv_bfloat16* dst = &g_Whh[dir][(size_t)c * 1024];
    *(uint2*)&dst[threadIdx.x * 4]       = *(const uint2*)hi4;
    *(uint2*)&dst[512 + threadIdx.x * 4] = *(const uint2*)lo4;
}

// ---------------- input-projection GEMM: fp16 2-term, K=2048 -----------------
// seg0 = A.hi x B.hi, seg1 = A.lo x B.hi. 128x256 tile, 512 thr, 3-stage.
#define SROW2 144
#define GA_TILE (128 * SROW2)        // 18432
#define GB_TILE (256 * SROW2)        // 36864
#define GSTG (GA_TILE + GB_TILE)     // 55296
#define G_SMEM (3 * GSTG)            // 165888
#define GKT 32

__global__ __launch_bounds__(512, 1)
void gemm_mma_kernel() {
    extern __shared__ __align__(16) char sm[];
    const uint32_t sbase = smem_u32(sm);

    const int tid  = threadIdx.x;
    const int wid  = tid >> 5;
    const int lane = tid & 31;
    const int nTile = blockIdx.x * 256;
    const int mTile = blockIdx.y * 128;

    // 16 warps: 2 m-halves x 8 n-strips, warp tile 64x32
    const int m0 = (wid & 1) * 64;
    const int n0 = (wid >> 1) * 32;

    const int lc8 = tid & 7;
    const int lr  = tid >> 3;            // 0..63
    const uint32_t aoff0 = (uint32_t)(lr * SROW2 + lc8 * 16);
    const uint32_t aoff1 = (uint32_t)((lr + 64) * SROW2 + lc8 * 16);
    const __half* __restrict__ gA = g_Xs + (size_t)mTile * KS2;
    const __half* __restrict__ gB = g_Ws + (size_t)nTile * KS2;

    auto issue_stage = [&](int kt) {
        const uint32_t sa = sbase + (kt % 3) * GSTG;
        const uint32_t sb = sa + GA_TILE;
        const int seg = kt >> 4;                 // 0: hi, 1: lo (A only)
        const int k64 = (kt & 15) * 64;
        const size_t acol = (size_t)((seg == 1) ? (DD + k64) : k64) + lc8 * 8;
        const size_t bcol = (size_t)k64 + lc8 * 8;
        CPA16(sa + aoff0, gA + (size_t)lr * KS2 + acol);
        CPA16(sa + aoff1, gA + (size_t)(lr + 64) * KS2 + acol);
#pragma unroll
        for (int q = 0; q < 4; q++) {
            const int row = lr + q * 64;
            CPA16(sb + aoff0 + (uint32_t)(q * 64 * SROW2),
                  gB + (size_t)row * KS2 + bcol);
        }
    };

    float acc[4][4][4];
#pragma unroll
    for (int i = 0; i < 4; i++)
#pragma unroll
        for (int j = 0; j < 4; j++)
#pragma unroll
            for (int q = 0; q < 4; q++) acc[i][j][q] = 0.f;

    const int r8 = lane & 7;
    const int tI = lane >> 3;
    const uint32_t aLaneOff = (uint32_t)((r8 + (tI & 1) * 8) * SROW2 + (tI >> 1) * 16);
    const uint32_t bLaneOff = (uint32_t)((r8 + (tI >> 1) * 8) * SROW2 + (tI & 1) * 16);

    issue_stage(0); CPA_COMMIT();
    issue_stage(1); CPA_COMMIT();

    for (int kt = 0; kt < GKT; kt++) {
        asm volatile("cp.async.wait_group 1;" ::: "memory");
        __syncthreads();

        const uint32_t sa = sbase + (kt % 3) * GSTG;
        const uint32_t sb = sa + GA_TILE;
#pragma unroll
        for (int kk = 0; kk < 4; kk++) {
            uint32_t afr[4][4], bfr[2][4];
#pragma unroll
            for (int mi = 0; mi < 4; mi++)
                ldmatrix_x4(afr[mi],
                            sa + (uint32_t)((m0 + mi * 16) * SROW2 + kk * 32) + aLaneOff);
#pragma unroll
            for (int nb = 0; nb < 2; nb++)
                ldmatrix_x4(bfr[nb],
                            sb + (uint32_t)((n0 + nb * 16) * SROW2 + kk * 32) + bLaneOff);
#pragma unroll
            for (int mi = 0; mi < 4; mi++)
#pragma unroll
                for (int ni = 0; ni < 4; ni++) {
                    const uint32_t* bp = &bfr[ni >> 1][(ni & 1) * 2];
                    mma16816h(acc[mi][ni], afr[mi], bp[0], bp[1]);
                }
        }
        if (kt + 2 < GKT) issue_stage(kt + 2);
        CPA_COMMIT();
    }

    const int gid = lane >> 2;
    const int tig = lane & 3;
#pragma unroll
    for (int mi = 0; mi < 4; mi++) {
        const int m = mTile + m0 + mi * 16 + gid;
#pragma unroll
        for (int ni = 0; ni < 4; ni++) {
            const int n = nTile + n0 + ni * 8 + tig * 2;
            const float2 bv = *(const float2*)&g_bias[n];
            float2 o0 = make_float2(acc[mi][ni][0] + bv.x, acc[mi][ni][1] + bv.y);
            float2 o1 = make_float2(acc[mi][ni][2] + bv.x, acc[mi][ni][3] + bv.y);
            *(float2*)&g_G[(size_t)m * GNF + n]       = o0;
            *(float2*)&g_G[(size_t)(m + 8) * GNF + n] = o1;
        }
    }
}

// ---------------- persistent recurrence (R15 winner, bf16 3-term) ------------
#define ST_A (64 * SROW2)
#define ST_B (64 * SROW2)
#define STG  (ST_A + ST_B)
#define NST 6
#define R12_SMEM (NST * STG)
#define NPAIR 12
#define SRBUF (64 * 68 * 4)
#define SROFF (4 * STG)

__global__ __launch_bounds__(256, 2)
void lstm_persistent(const int* __restrict__ x_len)
{
    extern __shared__ __align__(16) char sm[];
    const uint32_t sbase = smem_u32(sm);

    const int tid  = threadIdx.x;
    const int wid  = tid >> 5;
    const int lane = tid & 31;
    const int nTile = blockIdx.x * 64;
    const int b0    = blockIdx.y * 64;
    const int dir   = blockIdx.z;
    const int grp   = dir * 4 + blockIdx.y;

    const __nv_bfloat16* __restrict__ Wd = g_Whh[dir];
    float* __restrict__ outp = g_outd[dir];

    const int ksg = wid >> 2;
    const int w4  = wid & 3;
    const int m0  = (w4 & 1) * 32;
    const int n0  = (w4 >> 1) * 32;

    const int c0r = tid >> 3;
    const int c1r = (tid + 256) >> 3;
    const int c8  = (tid & 7);
    const uint32_t off0 = (uint32_t)(c0r * SROW2 + c8 * 16);
    const uint32_t off1 = (uint32_t)(c1r * SROW2 + c8 * 16);

    const int r8 = lane & 7;
    const int tI = lane >> 3;
    const uint32_t aLaneOff = (uint32_t)((r8 + (tI & 1) * 8) * SROW2 + (tI >> 1) * 16);
    const uint32_t bLaneOff = (uint32_t)((r8 + (tI >> 1) * 8) * SROW2 + (tI & 1) * 16);
    const int gid = lane >> 2;
    const int tig = lane & 3;
    const int jBase = nTile >> 2;

    float* __restrict__ sR0 = (float*)(sm + SROFF);
    float* __restrict__ sR1 = (float*)(sm + SROFF + SRBUF);
    float* __restrict__ sRme = ksg ? sR1 : sR0;

    float hreg[4] = {0.f, 0.f, 0.f, 0.f};
    float creg[4] = {0.f, 0.f, 0.f, 0.f};

    auto issue_B = [&](int kt) {
        const int stage = kt % NST;
        const int seg  = kt >> 3;
        const int ktk  = kt & 7;
        const int bcol = (seg == 2) ? (512 + ktk * 64) : (ktk * 64);
        const uint32_t sb = sbase + stage * STG + ST_A;
        CPA16(sb + off0, Wd + (size_t)(nTile + c0r) * 1024 + bcol + c8 * 8);
        CPA16(sb + off1, Wd + (size_t)(nTile + c1r) * 1024 + bcol + c8 * 8);
    };

    issue_B(0); issue_B(1); issue_B(2); issue_B(3); CPA_COMMIT();

    for (int t = 0; t < LL; t++) {
        const int p2 = t & 1;
        const __nv_bfloat16* __restrict__ hhi = g_hhi[dir][p2];
        const __nv_bfloat16* __restrict__ hlo = g_hlo[dir][p2];
        __nv_bfloat16* __restrict__ hhin = g_hhi[dir][p2 ^ 1];
        __nv_bfloat16* __restrict__ hlon = g_hlo[dir][p2 ^ 1];

        auto issue_A = [&](int kt) {
            const int stage = kt % NST;
            const int seg  = kt >> 3;
            const int acol = (kt & 7) * 64;
            const __nv_bfloat16* __restrict__ hsrc = (seg == 1) ? hlo : hhi;
            const uint32_t sa = sbase + stage * STG;
            CPA16(sa + off0, hsrc + (size_t)(b0 + c0r) * HH + acol + c8 * 8);
            CPA16(sa + off1, hsrc + (size_t)(b0 + c1r) * HH + acol + c8 * 8);
        };
        auto issue_AB = [&](int kt) { issue_A(kt); issue_B(kt); };

        float4 gp[4];
#pragma unroll
        for (int it = 0; it < 4; it++) {
            const int idx = it * 256 + tid;
            const int bl = idx >> 4;
            const int jj = idx & 15;
            const int b  = b0 + bl;
            const int len = x_len[b];
            int tq = t;
            if (dir) { tq = len - 1 - t; if (tq < 0) tq = 0; }
            gp[it] = *(const float4*)(
                g_G + ((size_t)tq * BB + b) * GNF + dir * G4H + (size_t)(jBase + jj) * 4);
        }

        float acc[2][4][4];
#pragma unroll
        for (int i = 0; i < 2; i++)
#pragma unroll
            for (int j = 0; j < 4; j++)
#pragma unroll
                for (int q = 0; q < 4; q++) acc[i][j][q] = 0.f;

        issue_A(0); issue_A(1); CPA_COMMIT();
        issue_A(2); issue_A(3); CPA_COMMIT();

        for (int p = 0; p < NPAIR; p++) {
            asm volatile("cp.async.wait_group 1;" ::: "memory");
            __syncthreads();

            const int kt = 2 * p + ksg;
            const uint32_t sa = sbase + (kt % NST) * STG;
            const uint32_t sb = sa + ST_A;
#pragma unroll
            for (int kk = 0; kk < 4; kk++) {
                uint32_t afr[2][4], bfr[2][4];
#pragma unroll
                for (int mi = 0; mi < 2; mi++)
                    ldmatrix_x4(afr[mi],
                                sa + (uint32_t)((m0 + mi * 16) * SROW2 + kk * 32) + aLaneOff);
#pragma unroll
                for (int nb = 0; nb < 2; nb++)
                    ldmatrix_x4(bfr[nb],
                                sb + (uint32_t)((n0 + nb * 16) * SROW2 + kk * 32) + bLaneOff);
#pragma unroll
                for (int mi = 0; mi < 2; mi++)
#pragma unroll
                    for (int ni = 0; ni < 4; ni++) {
                        const uint32_t* bp = &bfr[ni >> 1][(ni & 1) * 2];
                        mma16816(acc[mi][ni], afr[mi], bp[0], bp[1]);
                    }
            }
            if (p + 2 < NPAIR) { issue_AB(2 * p + 4); issue_AB(2 * p + 5); }
            CPA_COMMIT();
        }
        asm volatile("cp.async.wait_group 0;" ::: "memory");
        __syncthreads();

#pragma unroll
        for (int mi = 0; mi < 2; mi++) {
            const int row = m0 + mi * 16 + gid;
#pragma unroll
            for (int ni = 0; ni < 4; ni++) {
                const int col = n0 + ni * 8 + tig * 2;
                sRme[row * 68 + col]           = acc[mi][ni][0];
                sRme[row * 68 + col + 1]       = acc[mi][ni][1];
                sRme[(row + 8) * 68 + col]     = acc[mi][ni][2];
                sRme[(row + 8) * 68 + col + 1] = acc[mi][ni][3];
            }
        }
        __syncthreads();

#pragma unroll
        for (int it = 0; it < 4; it++) {
            const int idx = it * 256 + tid;
            const int bl = idx >> 4;
            const int jj = idx & 15;
            const int b  = b0 + bl;
            const int j  = jBase + jj;
            const int len = x_len[b];
            const float4 r0 = *(const float4*)&sR0[bl * 68 + jj * 4];
            const float4 r1 = *(const float4*)&sR1[bl * 68 + jj * 4];
            float i_ = fsigmoid(r0.x + r1.x + gp[it].x);
            float f_ = fsigmoid(r0.y + r1.y + gp[it].y);
            float g_ = ftanh(r0.z + r1.z + gp[it].z);
            float o_ = fsigmoid(r0.w + r1.w + gp[it].w);
            float cn = f_ * creg[it] + i_ * g_;
            float hn = o_ * ftanh(cn);
            const bool valid = (t < len);
            if (valid) { creg[it] = cn; hreg[it] = hn; }
            const float ho = hreg[it];
            const size_t hc = (size_t)b * HH + j;
            __nv_bfloat16 hi = __float2bfloat16_rn(ho);
            hhin[hc] = hi;
            hlon[hc] = __float2bfloat16_rn(ho - __bfloat162float(hi));
            outp[((size_t)b * LL + t) * HH + j] = valid ? hn : 0.f;
        }

        if (t + 1 < LL) {
            issue_B(0); issue_B(1); issue_B(2); issue_B(3);
        }
        CPA_COMMIT();

        group_barrier(grp, t);
    }
}

// ---------------- attention + head ------------------------------------------
__global__ __launch_bounds__(256)
void final_kernel(const float* __restrict__ x, const int* __restrict__ x_len,
                  const float* __restrict__ target_word,
                  const float* __restrict__ W_h, const float* __restrict__ b_tanh,
                  const float* __restrict__ W_lin, const float* __restrict__ b_lin,
                  const float* __restrict__ W_out, const float* __restrict__ b_out,
                  float* __restrict__ out)
{
    __shared__ float s_u[LL];
    __shared__ float s_ctx[2 * HH];
    __shared__ float s_lin[512];
    __shared__ float s_red[8];
    __shared__ float s_twdot;

    const int b    = blockIdx.x;
    const int tid  = threadIdx.x;
    const int warp = tid >> 5;
    const int lane = tid & 31;
    const int len  = x_len[b];

    {
        float partial = 0.f;
        for (int d = tid; d < DD; d += 256) {
            float s = 0.f;
#pragma unroll
            for (int k = 0; k < 5; k++)
                s += target_word[((size_t)b * 5 + k) * DD + d];
            partial = fmaf(s * 0.2f, W_h[DD + d], partial);
        }
#pragma unroll
        for (int off = 16; off; off >>= 1)
            partial += __shfl_xor_sync(0xffffffffu, partial, off);
        if (lane == 0) s_red[warp] = partial;
        __syncthreads();
        if (tid == 0) {
            float s = 0.f;
            for (int w = 0; w < 8; w++) s += s_red[w];
            s_twdot = s;
        }
        __syncthreads();
    }
    const float twdot = s_twdot;

    for (int i = 0; i < 16; i++) {
        const int t = warp * 16 + i;
        const float* xe = x + ((size_t)b * LL + t) * DD;
        float a = 0.f;
#pragma unroll 8
        for (int q = 0; q < 32; q++) {
            int d = lane + q * 32;
            a = fmaf(xe[d], W_h[d], a);
        }
#pragma unroll
        for (int off = 16; off; off >>= 1)
            a += __shfl_xor_sync(0xffffffffu, a, off);
        if (lane == 0)
            s_u[t] = (t < len) ? (a + twdot + b_tanh[t]) : -1e6f;
    }
    __syncthreads();

    if (warp == 0) {
        float v[4];
#pragma unroll
        for (int q = 0; q < 4; q++) v[q] = s_u[lane + q * 32];
        float m = fmaxf(fmaxf(v[0], v[1]), fmaxf(v[2], v[3]));
#pragma unroll
        for (int off = 16; off; off >>= 1)
            m = fmaxf(m, __shfl_xor_sync(0xffffffffu, m, off));
        float e[4], s = 0.f;
#pragma unroll
        for (int q = 0; q < 4; q++) { e[q] = expf(v[q] - m); s += e[q]; }
#pragma unroll
        for (int off = 16; off; off >>= 1)
            s += __shfl_xor_sync(0xffffffffu, s, off);
        float inv = 1.f / s;
#pragma unroll
        for (int q = 0; q < 4; q++) s_u[lane + q * 32] = e[q] * inv;
    }
    __syncthreads();

    {
        float accj[4] = {0.f, 0.f, 0.f, 0.f};
        const float* outf = g_outd[0] + (size_t)b * LL * HH;
        const float* outb = g_outd[1] + (size_t)b * LL * HH;
        for (int t = 0; t < LL; t++) {
            const float a = s_u[t];
            int t2 = len - 1 - t;
            if (t2 < 0) t2 = 0;
#pragma unroll
            for (int q = 0; q < 4; q++) {
                const int j = tid + q * 256;
                float hv;
                if (j < HH) hv = outf[(size_t)t * HH + j];
                else        hv = outb[(size_t)t2 * HH + (j - HH)];
                accj[q] = fmaf(a, hv, accj[q]);
            }
        }
#pragma unroll
        for (int q = 0; q < 4; q++) s_ctx[tid + q * 256] = accj[q];
    }
    __syncthreads();

    for (int i = 0; i < 64; i++) {
        const int o = warp * 64 + i;
        const float* wr = W_lin + (size_t)o * (2 * HH);
        float a = 0.f;
#pragma unroll 8
        for (int q = 0; q < 32; q++) {
            int d = lane + q * 32;
            a = fmaf(s_ctx[d], wr[d], a);
        }
#pragma unroll
        for (int off = 16; off; off >>= 1)
            a += __shfl_xor_sync(0xffffffffu, a, off);
        if (lane == 0) s_lin[o] = fmaxf(a + b_lin[o], 0.f);
    }
    __syncthreads();

    if (warp == 0) {
#pragma unroll
        for (int o = 0; o < 3; o++) {
            const float* wr = W_out + (size_t)o * 512;
            float a = 0.f;
#pragma unroll
            for (int q = 0; q < 16; q++) {
                int d = lane + q * 32;
                a = fmaf(s_lin[d], wr[d], a);
            }
#pragma unroll
            for (int off = 16; off; off >>= 1)
                a += __shfl_xor_sync(0xffffffffu, a, off);
            if (lane == 0) out[b * 3 + o] = a + b_out[o];
        }
    }
}

// ---------------- launch -----------------------------------------------------
extern "C" void kernel_launch(void* const* d_in, const int* in_sizes, int n_in,
                              void* d_out, int out_size)
{
    const float* x           = (const float*)d_in[0];
    const int*   x_len       = (const int*)d_in[1];
    const float* target_word = (const float*)d_in[3];
    const float* W_ih_f      = (const float*)d_in[5];
    const float* W_hh_f      = (const float*)d_in[6];
    const float* b_f         = (const float*)d_in[7];
    const float* W_ih_b      = (const float*)d_in[8];
    const float* W_hh_b      = (const float*)d_in[9];
    const float* b_b         = (const float*)d_in[10];
    const float* W_h         = (const float*)d_in[11];
    const float* b_tanh      = (const float*)d_in[12];
    const float* W_lin       = (const float*)d_in[13];
    const float* b_lin       = (const float*)d_in[14];
    const float* W_out       = (const float*)d_in[15];
    const float* b_out       = (const float*)d_in[16];
    float* out = (float*)d_out;

    static bool attr_set = false;
    if (!attr_set) {
        cudaFuncSetAttribute(lstm_persistent,
                             cudaFuncAttributeMaxDynamicSharedMemorySize, R12_SMEM);
        cudaFuncSetAttribute(gemm_mma_kernel,
                             cudaFuncAttributeMaxDynamicSharedMemorySize, G_SMEM);
        attr_set = true;
    }

    init_hc_kernel<<<(BB * HH + 255) / 256, 256>>>();
    convert_x_kernel<<<BB * LL, 256>>>(x);
    convert_w_kernel<<<GNF, 256>>>(W_ih_f, W_ih_b, b_f, b_b);
    {
        dim3 wgrid(G4H, 2);
        convert_whh_kernel<<<wgrid, 128>>>(W_hh_f, W_hh_b);
    }

    dim3 ggrid(GNF / 256, MM_TOT / 128);   // (16, 256) = 4096 blocks
    gemm_mma_kernel<<<ggrid, 512, G_SMEM>>>();

    dim3 sgrid(G4H / 64, BB / 64, 2);      // (32, 4, 2) = 256 persistent blocks
    lstm_persistent<<<sgrid, 256, R12_SMEM>>>(x_len);

    final_kernel<<<BB, 256>>>(x, x_len, target_word, W_h, b_tanh,
                              W_lin, b_lin, W_out, b_out, out);
}

// round 17
// speedup vs baseline: 1.9335x; 1.2390x over previous
#include <cuda_runtime.h>
#include <cuda_bf16.h>
#include <cuda_fp16.h>
#include <math.h>
#include <stdint.h>

// Problem dims
#define BB 256
#define LL 128
#define DD 1024
#define HH 512
#define G4H 2048
#define GNF 4096
#define KS2 2048            // compact [hi|lo] storage K (input GEMM)
#define MM_TOT (LL * BB)

// ---------------- scratch (device globals) ----------------------------------
__device__ float g_G[(size_t)MM_TOT * GNF];
__device__ float g_outd[2][(size_t)BB * LL * HH];
__device__ __half g_hhi[2][2][(size_t)BB * HH];        // fp16 h split
__device__ __half g_hlo[2][2][(size_t)BB * HH];
__device__ __half g_Xs[(size_t)MM_TOT * KS2];          // [m][ hi(1024) | lo(1024) ]
__device__ __half g_Ws[(size_t)GNF * KS2];             // [c][ hi(1024) | lo(1024) ]
__device__ __half g_Whh[2][(size_t)G4H * 512];         // [dir][c][ Whi(512) ] fp16
__device__ float g_bias[GNF];

struct GrpBar { unsigned int cnt; unsigned int gen; unsigned int pad[62]; };
__device__ GrpBar g_bars[8];

// ---------------- helpers ----------------------------------------------------
__device__ __forceinline__ uint32_t smem_u32(const void* p) {
    uint32_t a;
    asm("{ .reg .u64 t; cvta.to.shared.u64 t, %1; cvt.u32.u64 %0, t; }"
        : "=r"(a) : "l"(p));
    return a;
}
#define CPA16(dst, src) \
    asm volatile("cp.async.ca.shared.global [%0], [%1], 16;" :: "r"(dst), "l"(src))
#define CPA_COMMIT() asm volatile("cp.async.commit_group;" ::: "memory")

__device__ __forceinline__ void ldmatrix_x4(uint32_t* r, uint32_t addr) {
    asm volatile("ldmatrix.sync.aligned.m8n8.x4.shared.b16 {%0,%1,%2,%3}, [%4];"
                 : "=r"(r[0]), "=r"(r[1]), "=r"(r[2]), "=r"(r[3]) : "r"(addr));
}
// fp16 mma
__device__ __forceinline__ void mma16816h(float* c, const uint32_t* a,
                                          uint32_t b0, uint32_t b1) {
    asm volatile(
        "mma.sync.aligned.m16n8k16.row.col.f32.f16.f16.f32 "
        "{%0,%1,%2,%3}, {%4,%5,%6,%7}, {%8,%9}, {%0,%1,%2,%3};"
        : "+f"(c[0]), "+f"(c[1]), "+f"(c[2]), "+f"(c[3])
        : "r"(a[0]), "r"(a[1]), "r"(a[2]), "r"(a[3]), "r"(b0), "r"(b1));
}
__device__ __forceinline__ float fsigmoid(float x) {
    return __fdividef(1.f, 1.f + __expf(-x));
}
__device__ __forceinline__ float ftanh(float x) {
    float e2 = __expf(2.f * x);
    return __fdividef(e2 - 1.f, e2 + 1.f);
}

__device__ __forceinline__ void group_barrier(int gid, int step) {
    __syncthreads();
    if (threadIdx.x == 0) {
        __threadfence();
        unsigned int a = atomicAdd(&g_bars[gid].cnt, 1u);
        if (a == 31u) {
            g_bars[gid].cnt = 0;
            __threadfence();
            atomicExch(&g_bars[gid].gen, (unsigned)(step + 1));
        } else {
            unsigned int g;
            do {
                asm volatile("ld.acquire.gpu.u32 %0, [%1];"
                             : "=r"(g) : "l"(&g_bars[gid].gen));
                if (g > (unsigned)step) break;
                __nanosleep(32);
            } while (true);
        }
    }
    __syncthreads();
}

// ---------------- init -------------------------------------------------------
__global__ void init_hc_kernel() {
    int i = blockIdx.x * blockDim.x + threadIdx.x;
    if (i < 8) { g_bars[i].cnt = 0; g_bars[i].gen = 0; }
    if (i < BB * HH) {
        g_hhi[0][0][i] = __float2half_rn(0.f);
        g_hhi[1][0][i] = __float2half_rn(0.f);
        g_hlo[0][0][i] = __float2half_rn(0.f);
        g_hlo[1][0][i] = __float2half_rn(0.f);
    }
}

// ---------------- fp32 -> fp16 hi/lo split converters ------------------------
__global__ __launch_bounds__(256)
void convert_x_kernel(const float* __restrict__ X) {
    const int bt = blockIdx.x;
    const int b = bt >> 7;
    const int t = bt & 127;
    const float4 v = ((const float4*)(X + (size_t)bt * DD))[threadIdx.x];
    __half hi4[4], lo4[4];
    hi4[0] = __float2half_rn(v.x); lo4[0] = __float2half_rn(v.x - __half2float(hi4[0]));
    hi4[1] = __float2half_rn(v.y); lo4[1] = __float2half_rn(v.y - __half2float(hi4[1]));
    hi4[2] = __float2half_rn(v.z); lo4[2] = __float2half_rn(v.z - __half2float(hi4[2]));
    hi4[3] = __float2half_rn(v.w); lo4[3] = __float2half_rn(v.w - __half2float(hi4[3]));
    const size_t base = ((size_t)t * BB + b) * KS2 + threadIdx.x * 4;
    *(uint2*)&g_Xs[base]      = *(const uint2*)hi4;
    *(uint2*)&g_Xs[base + DD] = *(const uint2*)lo4;
}

__global__ __launch_bounds__(256)
void convert_w_kernel(const float* __restrict__ Wf, const float* __restrict__ Wb,
                      const float* __restrict__ bf, const float* __restrict__ bb) {
    const int c = blockIdx.x;
    const int dir = (c >= G4H);
    const int local = c - dir * G4H;
    const int j = local >> 2, gate = local & 3;
    const int srow = gate * HH + j;
    const float* src = dir ? (Wb + (size_t)srow * DD) : (Wf + (size_t)srow * DD);
    const float4 v = ((const float4*)src)[threadIdx.x];
    __half hi4[4], lo4[4];
    hi4[0] = __float2half_rn(v.x); lo4[0] = __float2half_rn(v.x - __half2float(hi4[0]));
    hi4[1] = __float2half_rn(v.y); lo4[1] = __float2half_rn(v.y - __half2float(hi4[1]));
    hi4[2] = __float2half_rn(v.z); lo4[2] = __float2half_rn(v.z - __half2float(hi4[2]));
    hi4[3] = __float2half_rn(v.w); lo4[3] = __float2half_rn(v.w - __half2float(hi4[3]));
    const size_t base = (size_t)c * KS2 + threadIdx.x * 4;
    *(uint2*)&g_Ws[base]      = *(const uint2*)hi4;
    *(uint2*)&g_Ws[base + DD] = *(const uint2*)lo4;
    if (threadIdx.x == 0)
        g_bias[c] = dir ? bb[srow] : bf[srow];
}

// W_hh: fp16 hi only, gate-interleaved rows
__global__ __launch_bounds__(128)
void convert_whh_kernel(const float* __restrict__ Wf, const float* __restrict__ Wb) {
    const int c   = blockIdx.x;
    const int dir = blockIdx.y;
    const int gate = c & 3, j = c >> 2;
    const float* __restrict__ W = dir ? Wb : Wf;
    const float4 v = ((const float4*)(W + (size_t)(gate * HH + j) * HH))[threadIdx.x];
    __half hi4[4];
    hi4[0] = __float2half_rn(v.x);
    hi4[1] = __float2half_rn(v.y);
    hi4[2] = __float2half_rn(v.z);
    hi4[3] = __float2half_rn(v.w);
    *(uint2*)&g_Whh[dir][(size_t)c * 512 + threadIdx.x * 4] = *(const uint2*)hi4;
}

// ---------------- input-projection GEMM: fp16 2-term, K=2048 (R16 winner) ----
#define SROW2 144
#define GA_TILE (128 * SROW2)        // 18432
#define GB_TILE (256 * SROW2)        // 36864
#define GSTG (GA_TILE + GB_TILE)     // 55296
#define G_SMEM (3 * GSTG)            // 165888
#define GKT 32

__global__ __launch_bounds__(512, 1)
void gemm_mma_kernel() {
    extern __shared__ __align__(16) char sm[];
    const uint32_t sbase = smem_u32(sm);

    const int tid  = threadIdx.x;
    const int wid  = tid >> 5;
    const int lane = tid & 31;
    const int nTile = blockIdx.x * 256;
    const int mTile = blockIdx.y * 128;

    const int m0 = (wid & 1) * 64;
    const int n0 = (wid >> 1) * 32;

    const int lc8 = tid & 7;
    const int lr  = tid >> 3;
    const uint32_t aoff0 = (uint32_t)(lr * SROW2 + lc8 * 16);
    const uint32_t aoff1 = (uint32_t)((lr + 64) * SROW2 + lc8 * 16);
    const __half* __restrict__ gA = g_Xs + (size_t)mTile * KS2;
    const __half* __restrict__ gB = g_Ws + (size_t)nTile * KS2;

    auto issue_stage = [&](int kt) {
        const uint32_t sa = sbase + (kt % 3) * GSTG;
        const uint32_t sb = sa + GA_TILE;
        const int seg = kt >> 4;
        const int k64 = (kt & 15) * 64;
        const size_t acol = (size_t)((seg == 1) ? (DD + k64) : k64) + lc8 * 8;
        const size_t bcol = (size_t)k64 + lc8 * 8;
        CPA16(sa + aoff0, gA + (size_t)lr * KS2 + acol);
        CPA16(sa + aoff1, gA + (size_t)(lr + 64) * KS2 + acol);
#pragma unroll
        for (int q = 0; q < 4; q++) {
            const int row = lr + q * 64;
            CPA16(sb + aoff0 + (uint32_t)(q * 64 * SROW2),
                  gB + (size_t)row * KS2 + bcol);
        }
    };

    float acc[4][4][4];
#pragma unroll
    for (int i = 0; i < 4; i++)
#pragma unroll
        for (int j = 0; j < 4; j++)
#pragma unroll
            for (int q = 0; q < 4; q++) acc[i][j][q] = 0.f;

    const int r8 = lane & 7;
    const int tI = lane >> 3;
    const uint32_t aLaneOff = (uint32_t)((r8 + (tI & 1) * 8) * SROW2 + (tI >> 1) * 16);
    const uint32_t bLaneOff = (uint32_t)((r8 + (tI >> 1) * 8) * SROW2 + (tI & 1) * 16);

    issue_stage(0); CPA_COMMIT();
    issue_stage(1); CPA_COMMIT();

    for (int kt = 0; kt < GKT; kt++) {
        asm volatile("cp.async.wait_group 1;" ::: "memory");
        __syncthreads();

        const uint32_t sa = sbase + (kt % 3) * GSTG;
        const uint32_t sb = sa + GA_TILE;
#pragma unroll
        for (int kk = 0; kk < 4; kk++) {
            uint32_t afr[4][4], bfr[2][4];
#pragma unroll
            for (int mi = 0; mi < 4; mi++)
                ldmatrix_x4(afr[mi],
                            sa + (uint32_t)((m0 + mi * 16) * SROW2 + kk * 32) + aLaneOff);
#pragma unroll
            for (int nb = 0; nb < 2; nb++)
                ldmatrix_x4(bfr[nb],
                            sb + (uint32_t)((n0 + nb * 16) * SROW2 + kk * 32) + bLaneOff);
#pragma unroll
            for (int mi = 0; mi < 4; mi++)
#pragma unroll
                for (int ni = 0; ni < 4; ni++) {
                    const uint32_t* bp = &bfr[ni >> 1][(ni & 1) * 2];
                    mma16816h(acc[mi][ni], afr[mi], bp[0], bp[1]);
                }
        }
        if (kt + 2 < GKT) issue_stage(kt + 2);
        CPA_COMMIT();
    }

    const int gid = lane >> 2;
    const int tig = lane & 3;
#pragma unroll
    for (int mi = 0; mi < 4; mi++) {
        const int m = mTile + m0 + mi * 16 + gid;
#pragma unroll
        for (int ni = 0; ni < 4; ni++) {
            const int n = nTile + n0 + ni * 8 + tig * 2;
            const float2 bv = *(const float2*)&g_bias[n];
            float2 o0 = make_float2(acc[mi][ni][0] + bv.x, acc[mi][ni][1] + bv.y);
            float2 o1 = make_float2(acc[mi][ni][2] + bv.x, acc[mi][ni][3] + bv.y);
            *(float2*)&g_G[(size_t)m * GNF + n]       = o0;
            *(float2*)&g_G[(size_t)(m + 8) * GNF + n] = o1;
        }
    }
}

// ---------------- persistent recurrence: fp16 2-term, K=1024 -----------------
// 16 k-tiles (seg0: hhi x Whi, seg1: hlo x Whi), 8 paired iterations,
// 6 stages, k-split warp groups, reg h/c state, pre-barrier B prefetch.
#define ST_A (64 * SROW2)
#define ST_B (64 * SROW2)
#define STG  (ST_A + ST_B)
#define NST 6
#define R17_SMEM (NST * STG)       // 110592
#define NPAIR 8
#define SRBUF (64 * 68 * 4)
#define SROFF (4 * STG)

__global__ __launch_bounds__(256, 2)
void lstm_persistent(const int* __restrict__ x_len)
{
    extern __shared__ __align__(16) char sm[];
    const uint32_t sbase = smem_u32(sm);

    const int tid  = threadIdx.x;
    const int wid  = tid >> 5;
    const int lane = tid & 31;
    const int nTile = blockIdx.x * 64;
    const int b0    = blockIdx.y * 64;
    const int dir   = blockIdx.z;
    const int grp   = dir * 4 + blockIdx.y;

    const __half* __restrict__ Wd = g_Whh[dir];
    float* __restrict__ outp = g_outd[dir];

    const int ksg = wid >> 2;
    const int w4  = wid & 3;
    const int m0  = (w4 & 1) * 32;
    const int n0  = (w4 >> 1) * 32;

    const int c0r = tid >> 3;
    const int c1r = (tid + 256) >> 3;
    const int c8  = (tid & 7);
    const uint32_t off0 = (uint32_t)(c0r * SROW2 + c8 * 16);
    const uint32_t off1 = (uint32_t)(c1r * SROW2 + c8 * 16);

    const int r8 = lane & 7;
    const int tI = lane >> 3;
    const uint32_t aLaneOff = (uint32_t)((r8 + (tI & 1) * 8) * SROW2 + (tI >> 1) * 16);
    const uint32_t bLaneOff = (uint32_t)((r8 + (tI >> 1) * 8) * SROW2 + (tI & 1) * 16);
    const int gid = lane >> 2;
    const int tig = lane & 3;
    const int jBase = nTile >> 2;

    float* __restrict__ sR0 = (float*)(sm + SROFF);
    float* __restrict__ sR1 = (float*)(sm + SROFF + SRBUF);
    float* __restrict__ sRme = ksg ? sR1 : sR0;

    float hreg[4] = {0.f, 0.f, 0.f, 0.f};
    float creg[4] = {0.f, 0.f, 0.f, 0.f};

    // B = Whi only; same columns for both segs (kt & 7)
    auto issue_B = [&](int kt) {
        const int stage = kt % NST;
        const int bcol = (kt & 7) * 64;
        const uint32_t sb = sbase + stage * STG + ST_A;
        CPA16(sb + off0, Wd + (size_t)(nTile + c0r) * 512 + bcol + c8 * 8);
        CPA16(sb + off1, Wd + (size_t)(nTile + c1r) * 512 + bcol + c8 * 8);
    };

    issue_B(0); issue_B(1); issue_B(2); issue_B(3); CPA_COMMIT();

    for (int t = 0; t < LL; t++) {
        const int p2 = t & 1;
        const __half* __restrict__ hhi = g_hhi[dir][p2];
        const __half* __restrict__ hlo = g_hlo[dir][p2];
        __half* __restrict__ hhin = g_hhi[dir][p2 ^ 1];
        __half* __restrict__ hlon = g_hlo[dir][p2 ^ 1];

        auto issue_A = [&](int kt) {
            const int stage = kt % NST;
            const int acol = (kt & 7) * 64;
            const __half* __restrict__ hsrc = (kt >> 3) ? hlo : hhi;
            const uint32_t sa = sbase + stage * STG;
            CPA16(sa + off0, hsrc + (size_t)(b0 + c0r) * HH + acol + c8 * 8);
            CPA16(sa + off1, hsrc + (size_t)(b0 + c1r) * HH + acol + c8 * 8);
        };
        auto issue_AB = [&](int kt) { issue_A(kt); issue_B(kt); };

        float4 gp[4];
#pragma unroll
        for (int it = 0; it < 4; it++) {
            const int idx = it * 256 + tid;
            const int bl = idx >> 4;
            const int jj = idx & 15;
            const int b  = b0 + bl;
            const int len = x_len[b];
            int tq = t;
            if (dir) { tq = len - 1 - t; if (tq < 0) tq = 0; }
            gp[it] = *(const float4*)(
                g_G + ((size_t)tq * BB + b) * GNF + dir * G4H + (size_t)(jBase + jj) * 4);
        }

        float acc[2][4][4];
#pragma unroll
        for (int i = 0; i < 2; i++)
#pragma unroll
            for (int j = 0; j < 4; j++)
#pragma unroll
                for (int q = 0; q < 4; q++) acc[i][j][q] = 0.f;

        issue_A(0); issue_A(1); CPA_COMMIT();
        issue_A(2); issue_A(3); CPA_COMMIT();

        for (int p = 0; p < NPAIR; p++) {
            asm volatile("cp.async.wait_group 1;" ::: "memory");
            __syncthreads();

            const int kt = 2 * p + ksg;
            const uint32_t sa = sbase + (kt % NST) * STG;
            const uint32_t sb = sa + ST_A;
#pragma unroll
            for (int kk = 0; kk < 4; kk++) {
                uint32_t afr[2][4], bfr[2][4];
#pragma unroll
                for (int mi = 0; mi < 2; mi++)
                    ldmatrix_x4(afr[mi],
                                sa + (uint32_t)((m0 + mi * 16) * SROW2 + kk * 32) + aLaneOff);
#pragma unroll
                for (int nb = 0; nb < 2; nb++)
                    ldmatrix_x4(bfr[nb],
                                sb + (uint32_t)((n0 + nb * 16) * SROW2 + kk * 32) + bLaneOff);
#pragma unroll
                for (int mi = 0; mi < 2; mi++)
#pragma unroll
                    for (int ni = 0; ni < 4; ni++) {
                        const uint32_t* bp = &bfr[ni >> 1][(ni & 1) * 2];
                        mma16816h(acc[mi][ni], afr[mi], bp[0], bp[1]);
                    }
            }
            if (p + 2 < NPAIR) { issue_AB(2 * p + 4); issue_AB(2 * p + 5); }
            CPA_COMMIT();
        }
        asm volatile("cp.async.wait_group 0;" ::: "memory");
        __syncthreads();

#pragma unroll
        for (int mi = 0; mi < 2; mi++) {
            const int row = m0 + mi * 16 + gid;
#pragma unroll
            for (int ni = 0; ni < 4; ni++) {
                const int col = n0 + ni * 8 + tig * 2;
                sRme[row * 68 + col]           = acc[mi][ni][0];
                sRme[row * 68 + col + 1]       = acc[mi][ni][1];
                sRme[(row + 8) * 68 + col]     = acc[mi][ni][2];
                sRme[(row + 8) * 68 + col + 1] = acc[mi][ni][3];
            }
        }
        __syncthreads();

#pragma unroll
        for (int it = 0; it < 4; it++) {
            const int idx = it * 256 + tid;
            const int bl = idx >> 4;
            const int jj = idx & 15;
            const int b  = b0 + bl;
            const int j  = jBase + jj;
            const int len = x_len[b];
            const float4 r0 = *(const float4*)&sR0[bl * 68 + jj * 4];
            const float4 r1 = *(const float4*)&sR1[bl * 68 + jj * 4];
            float i_ = fsigmoid(r0.x + r1.x + gp[it].x);
            float f_ = fsigmoid(r0.y + r1.y + gp[it].y);
            float g_ = ftanh(r0.z + r1.z + gp[it].z);
            float o_ = fsigmoid(r0.w + r1.w + gp[it].w);
            float cn = f_ * creg[it] + i_ * g_;
            float hn = o_ * ftanh(cn);
            const bool valid = (t < len);
            if (valid) { creg[it] = cn; hreg[it] = hn; }
            const float ho = hreg[it];
            const size_t hc = (size_t)b * HH + j;
            __half hi = __float2half_rn(ho);
            hhin[hc] = hi;
            hlon[hc] = __float2half_rn(ho - __half2float(hi));
            outp[((size_t)b * LL + t) * HH + j] = valid ? hn : 0.f;
        }

        if (t + 1 < LL) {
            issue_B(0); issue_B(1); issue_B(2); issue_B(3);
        }
        CPA_COMMIT();

        group_barrier(grp, t);
    }
}

// ---------------- attention + head ------------------------------------------
__global__ __launch_bounds__(256)
void final_kernel(const float* __restrict__ x, const int* __restrict__ x_len,
                  const float* __restrict__ target_word,
                  const float* __restrict__ W_h, const float* __restrict__ b_tanh,
                  const float* __restrict__ W_lin, const float* __restrict__ b_lin,
                  const float* __restrict__ W_out, const float* __restrict__ b_out,
                  float* __restrict__ out)
{
    __shared__ float s_u[LL];
    __shared__ float s_ctx[2 * HH];
    __shared__ float s_lin[512];
    __shared__ float s_red[8];
    __shared__ float s_twdot;

    const int b    = blockIdx.x;
    const int tid  = threadIdx.x;
    const int warp = tid >> 5;
    const int lane = tid & 31;
    const int len  = x_len[b];

    {
        float partial = 0.f;
        for (int d = tid; d < DD; d += 256) {
            float s = 0.f;
#pragma unroll
            for (int k = 0; k < 5; k++)
                s += target_word[((size_t)b * 5 + k) * DD + d];
            partial = fmaf(s * 0.2f, W_h[DD + d], partial);
        }
#pragma unroll
        for (int off = 16; off; off >>= 1)
            partial += __shfl_xor_sync(0xffffffffu, partial, off);
        if (lane == 0) s_red[warp] = partial;
        __syncthreads();
        if (tid == 0) {
            float s = 0.f;
            for (int w = 0; w < 8; w++) s += s_red[w];
            s_twdot = s;
        }
        __syncthreads();
    }
    const float twdot = s_twdot;

    for (int i = 0; i < 16; i++) {
        const int t = warp * 16 + i;
        const float* xe = x + ((size_t)b * LL + t) * DD;
        float a = 0.f;
#pragma unroll 8
        for (int q = 0; q < 32; q++) {
            int d = lane + q * 32;
            a = fmaf(xe[d], W_h[d], a);
        }
#pragma unroll
        for (int off = 16; off; off >>= 1)
            a += __shfl_xor_sync(0xffffffffu, a, off);
        if (lane == 0)
            s_u[t] = (t < len) ? (a + twdot + b_tanh[t]) : -1e6f;
    }
    __syncthreads();

    if (warp == 0) {
        float v[4];
#pragma unroll
        for (int q = 0; q < 4; q++) v[q] = s_u[lane + q * 32];
        float m = fmaxf(fmaxf(v[0], v[1]), fmaxf(v[2], v[3]));
#pragma unroll
        for (int off = 16; off; off >>= 1)
            m = fmaxf(m, __shfl_xor_sync(0xffffffffu, m, off));
        float e[4], s = 0.f;
#pragma unroll
        for (int q = 0; q < 4; q++) { e[q] = expf(v[q] - m); s += e[q]; }
#pragma unroll
        for (int off = 16; off; off >>= 1)
            s += __shfl_xor_sync(0xffffffffu, s, off);
        float inv = 1.f / s;
#pragma unroll
        for (int q = 0; q < 4; q++) s_u[lane + q * 32] = e[q] * inv;
    }
    __syncthreads();

    {
        float accj[4] = {0.f, 0.f, 0.f, 0.f};
        const float* outf = g_outd[0] + (size_t)b * LL * HH;
        const float* outb = g_outd[1] + (size_t)b * LL * HH;
        for (int t = 0; t < LL; t++) {
            const float a = s_u[t];
            int t2 = len - 1 - t;
            if (t2 < 0) t2 = 0;
#pragma unroll
            for (int q = 0; q < 4; q++) {
                const int j = tid + q * 256;
                float hv;
                if (j < HH) hv = outf[(size_t)t * HH + j];
                else        hv = outb[(size_t)t2 * HH + (j - HH)];
                accj[q] = fmaf(a, hv, accj[q]);
            }
        }
#pragma unroll
        for (int q = 0; q < 4; q++) s_ctx[tid + q * 256] = accj[q];
    }
    __syncthreads();

    for (int i = 0; i < 64; i++) {
        const int o = warp * 64 + i;
        const float* wr = W_lin + (size_t)o * (2 * HH);
        float a = 0.f;
#pragma unroll 8
        for (int q = 0; q < 32; q++) {
            int d = lane + q * 32;
            a = fmaf(s_ctx[d], wr[d], a);
        }
#pragma unroll
        for (int off = 16; off; off >>= 1)
            a += __shfl_xor_sync(0xffffffffu, a, off);
        if (lane == 0) s_lin[o] = fmaxf(a + b_lin[o], 0.f);
    }
    __syncthreads();

    if (warp == 0) {
#pragma unroll
        for (int o = 0; o < 3; o++) {
            const float* wr = W_out + (size_t)o * 512;
            float a = 0.f;
#pragma unroll
            for (int q = 0; q < 16; q++) {
                int d = lane + q * 32;
                a = fmaf(s_lin[d], wr[d], a);
            }
#pragma unroll
            for (int off = 16; off; off >>= 1)
                a += __shfl_xor_sync(0xffffffffu, a, off);
            if (lane == 0) out[b * 3 + o] = a + b_out[o];
        }
    }
}

// ---------------- launch -----------------------------------------------------
extern "C" void kernel_launch(void* const* d_in, const int* in_sizes, int n_in,
                              void* d_out, int out_size)
{
    const float* x           = (const float*)d_in[0];
    const int*   x_len       = (const int*)d_in[1];
    const float* target_word = (const float*)d_in[3];
    const float* W_ih_f      = (const float*)d_in[5];
    const float* W_hh_f      = (const float*)d_in[6];
    const float* b_f         = (const float*)d_in[7];
    const float* W_ih_b      = (const float*)d_in[8];
    const float* W_hh_b      = (const float*)d_in[9];
    const float* b_b         = (const float*)d_in[10];
    const float* W_h         = (const float*)d_in[11];
    const float* b_tanh      = (const float*)d_in[12];
    const float* W_lin       = (const float*)d_in[13];
    const float* b_lin       = (const float*)d_in[14];
    const float* W_out       = (const float*)d_in[15];
    const float* b_out       = (const float*)d_in[16];
    float* out = (float*)d_out;

    static bool attr_set = false;
    if (!attr_set) {
        cudaFuncSetAttribute(lstm_persistent,
                             cudaFuncAttributeMaxDynamicSharedMemorySize, R17_SMEM);
        cudaFuncSetAttribute(gemm_mma_kernel,
                             cudaFuncAttributeMaxDynamicSharedMemorySize, G_SMEM);
        attr_set = true;
    }

    init_hc_kernel<<<(BB * HH + 255) / 256, 256>>>();
    convert_x_kernel<<<BB * LL, 256>>>(x);
    convert_w_kernel<<<GNF, 256>>>(W_ih_f, W_ih_b, b_f, b_b);
    {
        dim3 wgrid(G4H, 2);
        convert_whh_kernel<<<wgrid, 128>>>(W_hh_f, W_hh_b);
    }

    dim3 ggrid(GNF / 256, MM_TOT / 128);   // (16, 256) = 4096 blocks
    gemm_mma_kernel<<<ggrid, 512, G_SMEM>>>();

    dim3 sgrid(G4H / 64, BB / 64, 2);      // (32, 4, 2) = 256 persistent blocks
    lstm_persistent<<<sgrid, 256, R17_SMEM>>>(x_len);

    final_kernel<<<BB, 256>>>(x, x_len, target_word, W_h, b_tanh,
                              W_lin, b_lin, W_out, b_out, out);
}